// round 14
// baseline (speedup 1.0000x reference)
#include <cuda_runtime.h>
#include <math.h>

#define NN 10000
#define HH 64
#define EE 40000
#define MD 12

typedef unsigned long long u64;
typedef unsigned int u32;

// ---------------- scratch (device globals; no allocation) ----------------
__device__ int   g_deg[4*NN];
__device__ int   g_start[4*NN];
__device__ int   g_cur[4*NN];
__device__ int   g_csr[4*EE];
__device__ int   g_nbr[4*NN*MD];
__device__ float g_sb[2][NN*HH];
__device__ float g_tb[2][NN*HH];
__device__ float g_agg[4][NN*HH];
__device__ float g_U[4][(NN+1)*256];
__device__ float g_Wp[12*64*256];     // permuted Whh: [blk][k][p]
__device__ float g_WihT[12*64*256];   // permuted Wih, k-major: [blk][k][p]
__device__ float g_bias2[12*256];     // bih+bhh, gate-permuted
// k-major transposed small weights
__device__ float g_WlT[12*64*64];
__device__ float g_WrT[12*64*64];
__device__ float g_Wg1T[128*64];
__device__ float g_Wm1T[80*64];
__device__ float g_Wm2T[64*32];
__device__ float g_Wm3T[32*2];
__device__ float g_E1sT[32*64];
__device__ float g_E2sT[64*64];
__device__ float g_E1tT[24*64];
__device__ float g_E2tT[64*64];

// gate-permuted index: p -> row of Wih/Whh (torch gate order i,f,g,o)
__device__ __forceinline__ int pmap_row(int p){
    return (p & 3) * 64 + 2 * ((p >> 2) & 31) + (p >> 7);
}
__device__ __forceinline__ float sigf(float x){
    return __fdividef(1.0f, 1.0f + __expf(-x));
}
__device__ __forceinline__ float tanhf_(float x){
    return fmaf(2.0f, __fdividef(1.0f, 1.0f + __expf(-2.0f*x)), -1.0f);
}

// ---------------- f32x2 packed helpers ----------------
__device__ __forceinline__ u64 pkf(float lo, float hi){
    u64 r; asm("mov.b64 %0, {%1,%2};" : "=l"(r) : "r"(__float_as_uint(lo)), "r"(__float_as_uint(hi))); return r;
}
__device__ __forceinline__ void upk(u64 v, float& lo, float& hi){
    u32 a, b;
    asm("mov.b64 {%0,%1}, %2;" : "=r"(a), "=r"(b) : "l"(v));
    lo = __uint_as_float(a); hi = __uint_as_float(b);
}
__device__ __forceinline__ u64 fma2_(u64 a, u64 b, u64 c){
    u64 d; asm("fma.rn.f32x2 %0, %1, %2, %3;" : "=l"(d) : "l"(a), "l"(b), "l"(c)); return d;
}

// shared U-phase: 256 threads, 32 nodes whose features sit in outs[32*64].
// Each thread owns gate-column p for all 32 nodes; blk selects (layer, et).
__device__ __forceinline__ void u_phase(const float* outs, int nb, int blk, int et){
    int p = threadIdx.x;
    const float* wt = g_WihT + (size_t)blk*16384;
    float w[64];
    #pragma unroll
    for(int k=0;k<64;k++) w[k] = wt[k*256 + p];
    float bias = g_bias2[blk*256 + p];
    float* U = g_U[et];
    for(int m=0;m<32;m++){
        int node = nb + m;
        if(node > NN) break;
        float acc = bias;
        const float4* xv = (const float4*)&outs[m*64];
        #pragma unroll
        for(int q=0;q<16;q++){
            float4 v = xv[q];
            acc = fmaf(v.x, w[4*q+0], acc);
            acc = fmaf(v.y, w[4*q+1], acc);
            acc = fmaf(v.z, w[4*q+2], acc);
            acc = fmaf(v.w, w[4*q+3], acc);
        }
        U[node*256 + p] = acc;
    }
}

// ---------------- graph preprocessing ----------------
// mega-prep: zero counters + Whh perm + Wih perm (k-major) + bias + all
// small-weight transposes. All sections independent.
__global__ void k_prep0(const float* __restrict__ Whh, const float* __restrict__ Wih,
                        const float* __restrict__ bih, const float* __restrict__ bhh,
                        const float* __restrict__ Wl, const float* __restrict__ Wr,
                        const float* __restrict__ Wg1, const float* __restrict__ Wm1,
                        const float* __restrict__ Wm2, const float* __restrict__ Wm3,
                        const float* __restrict__ E1s, const float* __restrict__ E2s,
                        const float* __restrict__ E1t, const float* __restrict__ E2t){
    int idx = blockIdx.x*blockDim.x + threadIdx.x;
    if(idx < 4*NN){ g_deg[idx] = 0; g_cur[idx] = 0; return; }
    idx -= 4*NN;
    if(idx < 12*16384){
        int i = idx >> 14; int r = idx & 16383; int k = r >> 8; int p = r & 255;
        g_Wp[idx] = Whh[i*16384 + pmap_row(p)*64 + k];
        return;
    }
    idx -= 12*16384;
    if(idx < 12*16384){
        int i = idx >> 14; int r = idx & 16383; int k = r >> 8; int p = r & 255;
        g_WihT[idx] = Wih[i*16384 + pmap_row(p)*64 + k];
        return;
    }
    idx -= 12*16384;
    if(idx < 12*256){
        int i = idx >> 8; int p = idx & 255; int row = pmap_row(p);
        g_bias2[idx] = bih[i*256 + row] + bhh[i*256 + row];
        return;
    }
    idx -= 12*256;
    if(idx < 49152){ int i=idx/4096, r=idx%4096, k=r/64, j=r%64; g_WlT[idx] = Wl[i*4096 + j*64 + k]; return; }
    idx -= 49152;
    if(idx < 49152){ int i=idx/4096, r=idx%4096, k=r/64, j=r%64; g_WrT[idx] = Wr[i*4096 + j*64 + k]; return; }
    idx -= 49152;
    if(idx < 8192){ int k=idx/64, j=idx%64; g_Wg1T[idx] = Wg1[j*128 + k]; return; }
    idx -= 8192;
    if(idx < 5120){ int k=idx/64, j=idx%64; g_Wm1T[idx] = Wm1[j*80 + k]; return; }
    idx -= 5120;
    if(idx < 2048){ int k=idx/32, j=idx%32; g_Wm2T[idx] = Wm2[j*64 + k]; return; }
    idx -= 2048;
    if(idx < 64){ int k=idx/2, j=idx%2; g_Wm3T[idx] = Wm3[j*32 + k]; return; }
    idx -= 64;
    if(idx < 2048){ int k=idx/64, j=idx%64; g_E1sT[idx] = E1s[j*32 + k]; return; }
    idx -= 2048;
    if(idx < 4096){ int k=idx/64, j=idx%64; g_E2sT[idx] = E2s[j*64 + k]; return; }
    idx -= 4096;
    if(idx < 1536){ int k=idx/64, j=idx%64; g_E1tT[idx] = E1t[j*24 + k]; return; }
    idx -= 1536;
    if(idx < 4096){ int k=idx/64, j=idx%64; g_E2tT[idx] = E2t[j*64 + k]; return; }
}
#define PREP0_TOTAL (4*NN + 2*12*16384 + 12*256 + 49152+49152+8192+5120+2048+64+2048+4096+1536+4096)

__global__ void k_degree(const int* __restrict__ edges){
    int i = blockIdx.x*blockDim.x + threadIdx.x;
    if(i >= 4*EE) return;
    int t = i / EE, e = i - t*EE;
    int dst = edges[t*2*EE + EE + e];
    atomicAdd(&g_deg[t*NN + dst], 1);
}

__global__ void k_scan(){
    __shared__ int sm[1024];
    int t = blockIdx.x, tid = threadIdx.x;
    const int CH = 10;
    int loc[CH]; int s = 0;
    int base = tid * CH;
    #pragma unroll
    for(int c=0;c<CH;c++){ int i = base + c; int v = (i<NN) ? g_deg[t*NN+i] : 0; loc[c] = v; s += v; }
    sm[tid] = s; __syncthreads();
    for(int off=1; off<1024; off<<=1){
        int v = (tid >= off) ? sm[tid-off] : 0;
        __syncthreads();
        sm[tid] += v;
        __syncthreads();
    }
    int run = sm[tid] - s;
    #pragma unroll
    for(int c=0;c<CH;c++){ int i = base + c; if(i < NN){ g_start[t*NN+i] = run; run += loc[c]; } }
}

__global__ void k_scatter(const int* __restrict__ edges){
    int i = blockIdx.x*blockDim.x + threadIdx.x;
    if(i >= 4*EE) return;
    int t = i / EE, e = i - t*EE;
    int src = edges[t*2*EE + e];
    int dst = edges[t*2*EE + EE + e];
    int p = atomicAdd(&g_cur[t*NN + dst], 1);
    g_csr[t*EE + g_start[t*NN + dst] + p] = src;
}

// top-12 smallest src per dst (incl. self loop), pad with sentinel NN
__global__ void k_buildnbr(){
    int i = blockIdx.x*blockDim.x + threadIdx.x;
    if(i >= 4*NN) return;
    int t = i / NN, n = i - t*NN;
    int arr[MD];
    #pragma unroll
    for(int k=0;k<MD;k++) arr[k] = 0x7fffffff;
    arr[0] = n;
    int st = g_start[t*NN + n], d = g_deg[t*NN + n];
    for(int q=0;q<d;q++){
        int v = g_csr[t*EE + st + q];
        if(v < arr[MD-1]){
            int j = MD-1;
            while(j > 0 && arr[j-1] > v){ arr[j] = arr[j-1]; j--; }
            arr[j] = v;
        }
    }
    int cnt = d + 1; if(cnt > MD) cnt = MD;
    #pragma unroll
    for(int k=0;k<MD;k++) g_nbr[i*MD + k] = (k < cnt) ? arr[k] : NN;
}

// ---------------- node encoder + fused U(layer 0) ----------------
__global__ void k_enc(const float* __restrict__ xs, const float* __restrict__ xt,
                      const float* __restrict__ b1s_, const float* __restrict__ b2s_,
                      const float* __restrict__ b1t_, const float* __restrict__ b2t_){
    __shared__ float W1T[32*64];
    __shared__ float W2T[64*64];
    __shared__ float xin[32*32];
    __shared__ float hid[32*64];
    __shared__ float b1s[64], b2s[64];
    __shared__ float outs[32*64];
    int isT = blockIdx.y;
    int K = isT ? 24 : 32;
    const float* x  = isT ? xt : xs;
    const float* b1 = isT ? b1t_ : b1s_;
    const float* b2 = isT ? b2t_ : b2s_;
    int tid = threadIdx.x;
    const float* w1src = isT ? g_E1tT : g_E1sT;
    const float* w2src = isT ? g_E2tT : g_E2sT;
    for(int i=tid;i<K*64;i+=256) W1T[i] = w1src[i];
    for(int i=tid;i<4096;i+=256) W2T[i] = w2src[i];
    if(tid < 64){ b1s[tid] = b1[tid]; b2s[tid] = b2[tid]; }
    int nb = blockIdx.x*32;
    for(int i=tid;i<32*K;i+=256){
        int node = nb + i/K;
        xin[i] = (node < NN) ? x[node*K + (i%K)] : 0.0f;
    }
    __syncthreads();
    int j = tid & 63, g = tid >> 6;
    #pragma unroll
    for(int mi=0;mi<8;mi++){
        int m = g*8 + mi;
        float a = b1s[j];
        for(int k=0;k<K;k++) a = fmaf(xin[m*K+k], W1T[k*64+j], a);
        hid[m*64+j] = fmaxf(a, 0.0f);
    }
    __syncthreads();
    float* out = isT ? g_tb[0] : g_sb[0];
    #pragma unroll
    for(int mi=0;mi<8;mi++){
        int m = g*8 + mi;
        int node = nb + m;
        float a = b2s[j];
        #pragma unroll 8
        for(int k=0;k<64;k++) a = fmaf(hid[m*64+k], W2T[k*64+j], a);
        bool ok = node < NN;
        outs[m*64+j] = ok ? a : 0.0f;
        if(ok) out[node*64+j] = a;
    }
    __syncthreads();
    // fused U for layer 0: source nodes feed ets {0,2}, target nodes {1,3}
    int etA = isT ? 1 : 0;
    int etB = isT ? 3 : 2;
    u_phase(outs, nb, etA, etA);
    u_phase(outs, nb, etB, etB);
}

// ---------------- LSTM aggregation (hot kernel, best: 6 nodes/warp) ----
__global__ void __launch_bounds__(256, 2) k_lstm(int L){
    extern __shared__ float smem[];
    float4* Wsm4 = (float4*)smem;            // 64KB
    float*  hsm  = smem + 16384;             // 48*64 = 12KB
    int et = blockIdx.y;
    int blk = L*4 + et;
    int tid = threadIdx.x;
    const float4* wp = (const float4*)(g_Wp + (size_t)blk*16384);
    #pragma unroll
    for(int r=0;r<16;r++) Wsm4[tid + r*256] = wp[tid + r*256];
    #pragma unroll
    for(int r=0;r<12;r++) hsm[tid + r*256] = 0.0f;
    __syncthreads();

    int warp = tid>>5, lane = tid&31;
    int nbase = blockIdx.x*48 + warp*6;
    const int* nbr = g_nbr + et*NN*MD;
    const float4* U4 = (const float4*)g_U[et];
    float c0[6], c1[6];
    int nodes[6];
    #pragma unroll
    for(int m=0;m<6;m++){
        c0[m]=0.f; c1[m]=0.f;
        int n = nbase+m; nodes[m] = (n<NN)?n:(NN-1);
    }
    float* hbase = hsm + warp*6*64;

    for(int t=0;t<MD;t++){
        u64 if0[6], go0[6], if1[6], go1[6];
        #pragma unroll
        for(int m=0;m<6;m++){
            int nb = __ldg(&nbr[nodes[m]*MD + t]);
            float4 a0 = __ldg(&U4[nb*64 + lane]);
            float4 a1 = __ldg(&U4[nb*64 + 32 + lane]);
            if0[m] = pkf(a0.x, a0.y); go0[m] = pkf(a0.z, a0.w);
            if1[m] = pkf(a1.x, a1.y); go1[m] = pkf(a1.z, a1.w);
        }
        #pragma unroll
        for(int k0=0;k0<64;k0+=4){
            float4 h4[6];
            #pragma unroll
            for(int m=0;m<6;m++) h4[m] = *(const float4*)&hbase[m*64 + k0];
            #pragma unroll
            for(int dk=0;dk<4;dk++){
                const ulonglong2 wa = *(const ulonglong2*)&Wsm4[(k0+dk)*64 + lane];
                const ulonglong2 wb = *(const ulonglong2*)&Wsm4[(k0+dk)*64 + 32 + lane];
                #pragma unroll
                for(int m=0;m<6;m++){
                    float hv = (dk==0)?h4[m].x:(dk==1)?h4[m].y:(dk==2)?h4[m].z:h4[m].w;
                    u64 hv2 = pkf(hv, hv);
                    if0[m] = fma2_(hv2, wa.x, if0[m]);
                    go0[m] = fma2_(hv2, wa.y, go0[m]);
                    if1[m] = fma2_(hv2, wb.x, if1[m]);
                    go1[m] = fma2_(hv2, wb.y, go1[m]);
                }
            }
        }
        __syncwarp();
        #pragma unroll
        for(int m=0;m<6;m++){
            float pi0, pf0, pg0, po0, pi1, pf1, pg1, po1;
            upk(if0[m], pi0, pf0); upk(go0[m], pg0, po0);
            upk(if1[m], pi1, pf1); upk(go1[m], pg1, po1);
            float i0=sigf(pi0), f0=sigf(pf0), g0=tanhf_(pg0), o0=sigf(po0);
            float i1=sigf(pi1), f1=sigf(pf1), g1=tanhf_(pg1), o1=sigf(po1);
            c0[m] = fmaf(f0, c0[m], i0*g0);
            c1[m] = fmaf(f1, c1[m], i1*g1);
            float h0 = o0*tanhf_(c0[m]);
            float h1 = o1*tanhf_(c1[m]);
            *(float2*)&hbase[m*64 + 2*lane] = make_float2(h0, h1);
        }
        __syncwarp();
    }
    float* agg = g_agg[et];
    #pragma unroll
    for(int m=0;m<6;m++){
        int n = nbase + m;
        if(n < NN){
            float2 hv = *(const float2*)&hbase[m*64 + 2*lane];
            ((float2*)(agg + n*64))[lane] = hv;
        }
    }
}

// ---- combine + fused U(next layer): 32 nodes/block; grid.y selects side ----
__global__ void k_comb(const float* __restrict__ bl, int L,
                       int inSel, int outSel, int useRes, int doU){
    extern __shared__ float cs[];
    float* WlAT = cs;
    float* WlBT = cs + 4096;
    float* WrST = cs + 8192;
    float* A    = cs + 12288;
    float* B    = cs + 14336;
    float* X    = cs + 16384;
    float* blj  = cs + 18432;
    float* OUTS = cs + 18496;    // 2048
    int v = blockIdx.y;          // 0: source side, 1: target side
    int ia = v ? (L*4+1) : (L*4+0);
    int ib = v ? (L*4+2) : (L*4+3);
    int etA = v ? 1 : 0;
    int etB = v ? 2 : 3;
    int isT = v;
    int tid = threadIdx.x;
    const float* wa = g_WlT + ia*4096;
    const float* wb = g_WlT + ib*4096;
    const float* ra = g_WrT + ia*4096;
    const float* rb = g_WrT + ib*4096;
    for(int i=tid;i<4096;i+=256){
        WlAT[i] = wa[i];
        WlBT[i] = wb[i];
        WrST[i] = ra[i] + rb[i];
    }
    if(tid < 64) blj[tid] = bl[ia*64+tid] + bl[ib*64+tid];
    int nb = blockIdx.x*32;
    const float* xin = isT ? g_tb[inSel] : g_sb[inSel];
    for(int i=tid;i<2048;i+=256){
        int node = nb + (i>>6); int c = i & 63;
        bool ok = node < NN;
        A[i] = ok ? g_agg[etA][node*64+c] : 0.0f;
        B[i] = ok ? g_agg[etB][node*64+c] : 0.0f;
        X[i] = ok ? xin[node*64+c] : 0.0f;
    }
    __syncthreads();
    int j = tid & 63, g = tid >> 6;
    float* out = isT ? g_tb[outSel] : g_sb[outSel];
    #pragma unroll
    for(int mi=0;mi<8;mi++){
        int m = g*8 + mi;
        int node = nb + m;
        float acc = blj[j];
        #pragma unroll 4
        for(int k=0;k<64;k++){
            acc = fmaf(A[m*64+k], WlAT[k*64+j], acc);
            acc = fmaf(B[m*64+k], WlBT[k*64+j], acc);
            acc = fmaf(X[m*64+k], WrST[k*64+j], acc);
        }
        acc *= 0.5f;
        if(useRes) acc += X[m*64+j];
        acc = fmaxf(acc, 0.0f);
        bool ok = node < NN;
        OUTS[m*64+j] = ok ? acc : 0.0f;
        if(ok) out[node*64+j] = acc;
    }
    if(doU){
        __syncthreads();
        int Ln = L + 1;
        int eA = isT ? 1 : 0;
        int eB = isT ? 3 : 2;
        u_phase(OUTS, nb, Ln*4 + eA, eA);
        u_phase(OUTS, nb, Ln*4 + eB, eB);
    }
}

// ---- edge head: 32 edges/block, smem k-major weights ----
__global__ void k_edge(const int* __restrict__ edges, const float* __restrict__ ea,
    const float* __restrict__ bg1, const float* __restrict__ Wg2, const float* __restrict__ bg2,
    const float* __restrict__ bm1, const float* __restrict__ bm2, const float* __restrict__ bm3,
    float* __restrict__ out){
    extern __shared__ float es[];
    float* Wg1T = es;               // 8192
    float* Wm1T = es + 8192;        // 5120
    float* Wm2T = es + 13312;       // 2048
    float* Wm3T = es + 15360;       // 64
    float* cvec = es + 15424;       // 256
    float* se   = es + 15680;       // 2048
    float* te   = es + 17728;       // 2048
    float* cat  = es + 19776;       // 2560
    float* h1   = es + 22336;       // 2048
    float* h2   = es + 24384;       // 1024
    float* red  = es + 25408;       // 64
    __shared__ int sidx[32], tidx[32];
    int tid = threadIdx.x;
    for(int i=tid;i<8192;i+=256) Wg1T[i] = g_Wg1T[i];
    for(int i=tid;i<5120;i+=256) Wm1T[i] = g_Wm1T[i];
    for(int i=tid;i<2048;i+=256) Wm2T[i] = g_Wm2T[i];
    if(tid < 64)  Wm3T[tid] = g_Wm3T[tid];
    if(tid < 64)  cvec[tid] = bg1[tid];
    else if(tid < 128) cvec[tid] = Wg2[tid-64];
    else if(tid < 192) cvec[tid] = bm1[tid-128];
    else if(tid < 224) cvec[tid] = bm2[tid-192];
    else if(tid == 224) cvec[224] = bm3[0];
    else if(tid == 225) cvec[225] = bm3[1];
    else if(tid == 226) cvec[226] = bg2[0];
    int ebase = blockIdx.x*32;
    if(tid < 32){
        sidx[tid] = edges[4*EE + ebase + tid];
        tidx[tid] = edges[5*EE + ebase + tid];
    }
    __syncthreads();
    for(int i=tid;i<2048;i+=256){
        int e = i >> 6, c = i & 63;
        se[i] = g_sb[1][sidx[e]*64 + c];
        te[i] = g_tb[1][tidx[e]*64 + c];
    }
    __syncthreads();
    int j = tid & 63, g = tid >> 6;
    int half = (tid >> 5) & 1;
    // Phase A: gate hidden dot Wg2, warp-reduced
    #pragma unroll
    for(int ei=0;ei<8;ei++){
        int e = g*8 + ei;
        float a = cvec[j];
        #pragma unroll 4
        for(int k=0;k<64;k++) a = fmaf(se[e*64+k], Wg1T[k*64+j], a);
        #pragma unroll 4
        for(int k=0;k<64;k++) a = fmaf(te[e*64+k], Wg1T[(64+k)*64+j], a);
        a = fmaxf(a, 0.0f);
        float v = a * cvec[64+j];
        #pragma unroll
        for(int off=16;off>0;off>>=1) v += __shfl_xor_sync(0xffffffffu, v, off);
        if((tid & 31) == 0) red[e*2 + half] = v;
    }
    __syncthreads();
    // Phase B: gate value, er || ea
    #pragma unroll
    for(int ei=0;ei<8;ei++){
        int e = g*8 + ei;
        float gv = sigf(red[e*2] + red[e*2+1] + cvec[226]);
        cat[e*80 + j] = gv*se[e*64+j] + (1.0f-gv)*te[e*64+j];
        if(j < 16) cat[e*80 + 64 + j] = ea[(ebase+e)*16 + j];
    }
    __syncthreads();
    // Phase C: m1
    #pragma unroll
    for(int ei=0;ei<8;ei++){
        int e = g*8 + ei;
        float m = cvec[128+j];
        #pragma unroll 4
        for(int k=0;k<80;k++) m = fmaf(cat[e*80+k], Wm1T[k*64+j], m);
        h1[e*64+j] = fmaxf(m, 0.0f);
    }
    __syncthreads();
    // Phase D: m2 (j<32)
    if(j < 32){
        #pragma unroll
        for(int ei=0;ei<8;ei++){
            int e = g*8 + ei;
            float m = cvec[192+j];
            #pragma unroll 4
            for(int k=0;k<64;k++) m = fmaf(h1[e*64+k], Wm2T[k*32+j], m);
            h2[e*32+j] = fmaxf(m, 0.0f);
        }
    }
    __syncthreads();
    // Phase E: m3 (j<2)
    if(j < 2){
        #pragma unroll
        for(int ei=0;ei<8;ei++){
            int e = g*8 + ei;
            float o = cvec[224+j];
            #pragma unroll
            for(int k=0;k<32;k++) o = fmaf(h2[e*32+k], Wm3T[k*2+j], o);
            out[(ebase+e)*2 + j] = o;
        }
    }
}

// ---------------- host launcher ----------------
extern "C" void kernel_launch(void* const* d_in, const int* in_sizes, int n_in,
                              void* d_out, int out_size){
    const float* x_source = (const float*)d_in[0];
    const float* x_target = (const float*)d_in[1];
    const int*   edges    = (const int*)  d_in[2];
    const float* ea       = (const float*)d_in[3];
    const float* We_s1=(const float*)d_in[4];  const float* be_s1=(const float*)d_in[5];
    const float* We_s2=(const float*)d_in[6];  const float* be_s2=(const float*)d_in[7];
    const float* We_t1=(const float*)d_in[8];  const float* be_t1=(const float*)d_in[9];
    const float* We_t2=(const float*)d_in[10]; const float* be_t2=(const float*)d_in[11];
    const float* Wih=(const float*)d_in[12];   const float* Whh=(const float*)d_in[13];
    const float* bih=(const float*)d_in[14];   const float* bhh=(const float*)d_in[15];
    const float* Wl =(const float*)d_in[16];   const float* bl =(const float*)d_in[17];
    const float* Wr =(const float*)d_in[18];
    const float* Wg1=(const float*)d_in[19];   const float* bg1=(const float*)d_in[20];
    const float* Wg2=(const float*)d_in[21];   const float* bg2=(const float*)d_in[22];
    const float* Wm1=(const float*)d_in[23];   const float* bm1=(const float*)d_in[24];
    const float* Wm2=(const float*)d_in[25];   const float* bm2=(const float*)d_in[26];
    const float* Wm3=(const float*)d_in[27];   const float* bm3=(const float*)d_in[28];
    float* out = (float*)d_out;

    cudaFuncSetAttribute(k_lstm, cudaFuncAttributeMaxDynamicSharedMemorySize, 77824);
    cudaFuncSetAttribute(k_comb, cudaFuncAttributeMaxDynamicSharedMemorySize, 82176);
    cudaFuncSetAttribute(k_edge, cudaFuncAttributeMaxDynamicSharedMemorySize, 102400);

    k_prep0   <<<(PREP0_TOTAL+255)/256, 256>>>(Whh, Wih, bih, bhh,
                                               Wl, Wr, Wg1, Wm1, Wm2, Wm3,
                                               We_s1, We_s2, We_t1, We_t2);
    k_degree  <<<(4*EE+255)/256, 256>>>(edges);
    k_scan    <<<4, 1024>>>();
    k_scatter <<<(4*EE+255)/256, 256>>>(edges);
    k_buildnbr<<<(4*NN+127)/128, 128>>>();
    k_enc     <<<dim3(313,2), 256>>>(x_source, x_target, be_s1, be_s2, be_t1, be_t2);

    for(int L=0; L<3; L++){
        int in = L & 1, o = 1 - in;
        k_lstm<<<dim3(209,4), 256, 77824>>>(L);
        k_comb<<<dim3(313,2), 256, 82176>>>(bl, L, in, o, (L>0)?1:0, (L<2)?1:0);
    }
    k_edge<<<1250, 256, 102400>>>(edges, ea, bg1, Wg2, bg2, bm1, bm2, bm3, out);
}

// round 15
// speedup vs baseline: 1.0392x; 1.0392x over previous
#include <cuda_runtime.h>
#include <math.h>

#define NN 10000
#define HH 64
#define EE 40000
#define MD 12

typedef unsigned long long u64;
typedef unsigned int u32;

// ---------------- scratch (device globals; no allocation) ----------------
__device__ int   g_deg[4*NN];
__device__ int   g_start[4*NN];
__device__ int   g_cur[4*NN];
__device__ int   g_csr[4*EE];
__device__ int   g_nbr[4*NN*MD];
__device__ float g_sb[2][NN*HH];
__device__ float g_tb[2][NN*HH];
__device__ float g_agg[4][NN*HH];
__device__ float g_U[4][(NN+1)*256];
__device__ float g_Wp[12*64*256];     // permuted Whh: [blk][k][p]
__device__ float g_WihT[12*64*256];   // permuted Wih, k-major: [blk][k][p]
__device__ float g_bias2[12*256];     // bih+bhh, gate-permuted
// k-major transposed small weights
__device__ float g_WlT[12*64*64];
__device__ float g_WrT[12*64*64];
__device__ float g_Wg1T[128*64];
__device__ float g_Wm1T[80*64];
__device__ float g_Wm2T[64*32];
__device__ float g_Wm3T[32*2];
__device__ float g_E1sT[32*64];
__device__ float g_E2sT[64*64];
__device__ float g_E1tT[24*64];
__device__ float g_E2tT[64*64];

// gate-permuted index: p -> row of Wih/Whh (torch gate order i,f,g,o)
__device__ __forceinline__ int pmap_row(int p){
    return (p & 3) * 64 + 2 * ((p >> 2) & 31) + (p >> 7);
}
__device__ __forceinline__ float sigf(float x){
    return __fdividef(1.0f, 1.0f + __expf(-x));
}
__device__ __forceinline__ float tanhf_(float x){
    return fmaf(2.0f, __fdividef(1.0f, 1.0f + __expf(-2.0f*x)), -1.0f);
}

// ---------------- f32x2 packed helpers ----------------
__device__ __forceinline__ u64 pkf(float lo, float hi){
    u64 r; asm("mov.b64 %0, {%1,%2};" : "=l"(r) : "r"(__float_as_uint(lo)), "r"(__float_as_uint(hi))); return r;
}
__device__ __forceinline__ void upk(u64 v, float& lo, float& hi){
    u32 a, b;
    asm("mov.b64 {%0,%1}, %2;" : "=r"(a), "=r"(b) : "l"(v));
    lo = __uint_as_float(a); hi = __uint_as_float(b);
}
__device__ __forceinline__ u64 fma2_(u64 a, u64 b, u64 c){
    u64 d; asm("fma.rn.f32x2 %0, %1, %2, %3;" : "=l"(d) : "l"(a), "l"(b), "l"(c)); return d;
}

// ---------------- graph preprocessing ----------------
// mega-prep: zero counters + Whh perm + Wih perm (k-major) + bias + all
// small-weight transposes. All sections independent.
__global__ void k_prep0(const float* __restrict__ Whh, const float* __restrict__ Wih,
                        const float* __restrict__ bih, const float* __restrict__ bhh,
                        const float* __restrict__ Wl, const float* __restrict__ Wr,
                        const float* __restrict__ Wg1, const float* __restrict__ Wm1,
                        const float* __restrict__ Wm2, const float* __restrict__ Wm3,
                        const float* __restrict__ E1s, const float* __restrict__ E2s,
                        const float* __restrict__ E1t, const float* __restrict__ E2t){
    int idx = blockIdx.x*blockDim.x + threadIdx.x;
    if(idx < 4*NN){ g_deg[idx] = 0; g_cur[idx] = 0; return; }
    idx -= 4*NN;
    if(idx < 12*16384){
        int i = idx >> 14; int r = idx & 16383; int k = r >> 8; int p = r & 255;
        g_Wp[idx] = Whh[i*16384 + pmap_row(p)*64 + k];
        return;
    }
    idx -= 12*16384;
    if(idx < 12*16384){
        int i = idx >> 14; int r = idx & 16383; int k = r >> 8; int p = r & 255;
        g_WihT[idx] = Wih[i*16384 + pmap_row(p)*64 + k];
        return;
    }
    idx -= 12*16384;
    if(idx < 12*256){
        int i = idx >> 8; int p = idx & 255; int row = pmap_row(p);
        g_bias2[idx] = bih[i*256 + row] + bhh[i*256 + row];
        return;
    }
    idx -= 12*256;
    if(idx < 49152){ int i=idx/4096, r=idx%4096, k=r/64, j=r%64; g_WlT[idx] = Wl[i*4096 + j*64 + k]; return; }
    idx -= 49152;
    if(idx < 49152){ int i=idx/4096, r=idx%4096, k=r/64, j=r%64; g_WrT[idx] = Wr[i*4096 + j*64 + k]; return; }
    idx -= 49152;
    if(idx < 8192){ int k=idx/64, j=idx%64; g_Wg1T[idx] = Wg1[j*128 + k]; return; }
    idx -= 8192;
    if(idx < 5120){ int k=idx/64, j=idx%64; g_Wm1T[idx] = Wm1[j*80 + k]; return; }
    idx -= 5120;
    if(idx < 2048){ int k=idx/32, j=idx%32; g_Wm2T[idx] = Wm2[j*64 + k]; return; }
    idx -= 2048;
    if(idx < 64){ int k=idx/2, j=idx%2; g_Wm3T[idx] = Wm3[j*32 + k]; return; }
    idx -= 64;
    if(idx < 2048){ int k=idx/64, j=idx%64; g_E1sT[idx] = E1s[j*32 + k]; return; }
    idx -= 2048;
    if(idx < 4096){ int k=idx/64, j=idx%64; g_E2sT[idx] = E2s[j*64 + k]; return; }
    idx -= 4096;
    if(idx < 1536){ int k=idx/64, j=idx%64; g_E1tT[idx] = E1t[j*24 + k]; return; }
    idx -= 1536;
    if(idx < 4096){ int k=idx/64, j=idx%64; g_E2tT[idx] = E2t[j*64 + k]; return; }
}
#define PREP0_TOTAL (4*NN + 2*12*16384 + 12*256 + 49152+49152+8192+5120+2048+64+2048+4096+1536+4096)

__global__ void k_degree(const int* __restrict__ edges){
    int i = blockIdx.x*blockDim.x + threadIdx.x;
    if(i >= 4*EE) return;
    int t = i / EE, e = i - t*EE;
    int dst = edges[t*2*EE + EE + e];
    atomicAdd(&g_deg[t*NN + dst], 1);
}

__global__ void k_scan(){
    __shared__ int sm[1024];
    int t = blockIdx.x, tid = threadIdx.x;
    const int CH = 10;
    int loc[CH]; int s = 0;
    int base = tid * CH;
    #pragma unroll
    for(int c=0;c<CH;c++){ int i = base + c; int v = (i<NN) ? g_deg[t*NN+i] : 0; loc[c] = v; s += v; }
    sm[tid] = s; __syncthreads();
    for(int off=1; off<1024; off<<=1){
        int v = (tid >= off) ? sm[tid-off] : 0;
        __syncthreads();
        sm[tid] += v;
        __syncthreads();
    }
    int run = sm[tid] - s;
    #pragma unroll
    for(int c=0;c<CH;c++){ int i = base + c; if(i < NN){ g_start[t*NN+i] = run; run += loc[c]; } }
}

__global__ void k_scatter(const int* __restrict__ edges){
    int i = blockIdx.x*blockDim.x + threadIdx.x;
    if(i >= 4*EE) return;
    int t = i / EE, e = i - t*EE;
    int src = edges[t*2*EE + e];
    int dst = edges[t*2*EE + EE + e];
    int p = atomicAdd(&g_cur[t*NN + dst], 1);
    g_csr[t*EE + g_start[t*NN + dst] + p] = src;
}

// top-12 smallest src per dst (incl. self loop), pad with sentinel NN
__global__ void k_buildnbr(){
    int i = blockIdx.x*blockDim.x + threadIdx.x;
    if(i >= 4*NN) return;
    int t = i / NN, n = i - t*NN;
    int arr[MD];
    #pragma unroll
    for(int k=0;k<MD;k++) arr[k] = 0x7fffffff;
    arr[0] = n;
    int st = g_start[t*NN + n], d = g_deg[t*NN + n];
    for(int q=0;q<d;q++){
        int v = g_csr[t*EE + st + q];
        if(v < arr[MD-1]){
            int j = MD-1;
            while(j > 0 && arr[j-1] > v){ arr[j] = arr[j-1]; j--; }
            arr[j] = v;
        }
    }
    int cnt = d + 1; if(cnt > MD) cnt = MD;
    #pragma unroll
    for(int k=0;k<MD;k++) g_nbr[i*MD + k] = (k < cnt) ? arr[k] : NN;
}

// ---------------- node encoder: 32 nodes/block, both types via grid.y ----
__global__ void k_enc(const float* __restrict__ xs, const float* __restrict__ xt,
                      const float* __restrict__ b1s_, const float* __restrict__ b2s_,
                      const float* __restrict__ b1t_, const float* __restrict__ b2t_){
    __shared__ float W1T[32*64];
    __shared__ float W2T[64*64];
    __shared__ float xin[32*32];
    __shared__ float hid[32*64];
    __shared__ float b1s[64], b2s[64];
    int isT = blockIdx.y;
    int K = isT ? 24 : 32;
    const float* x  = isT ? xt : xs;
    const float* b1 = isT ? b1t_ : b1s_;
    const float* b2 = isT ? b2t_ : b2s_;
    int tid = threadIdx.x;
    const float* w1src = isT ? g_E1tT : g_E1sT;
    const float* w2src = isT ? g_E2tT : g_E2sT;
    for(int i=tid;i<K*64;i+=256) W1T[i] = w1src[i];
    for(int i=tid;i<4096;i+=256) W2T[i] = w2src[i];
    if(tid < 64){ b1s[tid] = b1[tid]; b2s[tid] = b2[tid]; }
    int nb = blockIdx.x*32;
    for(int i=tid;i<32*K;i+=256){
        int node = nb + i/K;
        xin[i] = (node < NN) ? x[node*K + (i%K)] : 0.0f;
    }
    __syncthreads();
    int j = tid & 63, g = tid >> 6;
    #pragma unroll
    for(int mi=0;mi<8;mi++){
        int m = g*8 + mi;
        float a = b1s[j];
        for(int k=0;k<K;k++) a = fmaf(xin[m*K+k], W1T[k*64+j], a);
        hid[m*64+j] = fmaxf(a, 0.0f);
    }
    __syncthreads();
    float* out = isT ? g_tb[0] : g_sb[0];
    #pragma unroll
    for(int mi=0;mi<8;mi++){
        int m = g*8 + mi;
        int node = nb + m;
        float a = b2s[j];
        #pragma unroll 8
        for(int k=0;k<64;k++) a = fmaf(hid[m*64+k], W2T[k*64+j], a);
        if(node < NN) out[node*64+j] = a;
    }
}

// ---- U = X @ Wih^T + bias (gate-permuted); W column register-resident ----
__global__ void k_U(int L, int inSel){
    int et = blockIdx.y;
    int blk = L*4 + et;
    int isT = (et==1 || et==3);
    const float* x = isT ? g_tb[inSel] : g_sb[inSel];
    float* U = g_U[et];
    __shared__ float4 xsm[64*16];
    int p = threadIdx.x;
    float w[64];
    const float* wt = g_WihT + (size_t)blk*16384;
    #pragma unroll
    for(int k=0;k<64;k++) w[k] = wt[k*256 + p];
    float bias = g_bias2[blk*256 + p];
    int nb = blockIdx.x * 64;
    #pragma unroll
    for(int r=0;r<4;r++){
        int idx = p + r*256;
        int node = nb + (idx >> 4);
        float4 v = make_float4(0,0,0,0);
        if(node < NN) v = ((const float4*)x)[node*16 + (idx & 15)];
        xsm[idx] = v;
    }
    __syncthreads();
    for(int m=0;m<64;m++){
        int node = nb + m;
        if(node > NN) break;
        float acc = bias;
        #pragma unroll
        for(int q=0;q<16;q++){
            float4 xv = xsm[m*16 + q];
            acc = fmaf(xv.x, w[4*q+0], acc);
            acc = fmaf(xv.y, w[4*q+1], acc);
            acc = fmaf(xv.z, w[4*q+2], acc);
            acc = fmaf(xv.w, w[4*q+3], acc);
        }
        U[node*256 + p] = acc;
    }
}

// ---------------- LSTM aggregation (hot kernel, best: 6 nodes/warp) ----
__global__ void __launch_bounds__(256, 2) k_lstm(int L){
    extern __shared__ float smem[];
    float4* Wsm4 = (float4*)smem;            // 64KB
    float*  hsm  = smem + 16384;             // 48*64 = 12KB
    int et = blockIdx.y;
    int blk = L*4 + et;
    int tid = threadIdx.x;
    const float4* wp = (const float4*)(g_Wp + (size_t)blk*16384);
    #pragma unroll
    for(int r=0;r<16;r++) Wsm4[tid + r*256] = wp[tid + r*256];
    #pragma unroll
    for(int r=0;r<12;r++) hsm[tid + r*256] = 0.0f;
    __syncthreads();

    int warp = tid>>5, lane = tid&31;
    int nbase = blockIdx.x*48 + warp*6;
    const int* nbr = g_nbr + et*NN*MD;
    const float4* U4 = (const float4*)g_U[et];
    float c0[6], c1[6];
    int nodes[6];
    #pragma unroll
    for(int m=0;m<6;m++){
        c0[m]=0.f; c1[m]=0.f;
        int n = nbase+m; nodes[m] = (n<NN)?n:(NN-1);
    }
    float* hbase = hsm + warp*6*64;

    for(int t=0;t<MD;t++){
        u64 if0[6], go0[6], if1[6], go1[6];
        #pragma unroll
        for(int m=0;m<6;m++){
            int nb = __ldg(&nbr[nodes[m]*MD + t]);
            float4 a0 = __ldg(&U4[nb*64 + lane]);
            float4 a1 = __ldg(&U4[nb*64 + 32 + lane]);
            if0[m] = pkf(a0.x, a0.y); go0[m] = pkf(a0.z, a0.w);
            if1[m] = pkf(a1.x, a1.y); go1[m] = pkf(a1.z, a1.w);
        }
        #pragma unroll
        for(int k0=0;k0<64;k0+=4){
            float4 h4[6];
            #pragma unroll
            for(int m=0;m<6;m++) h4[m] = *(const float4*)&hbase[m*64 + k0];
            #pragma unroll
            for(int dk=0;dk<4;dk++){
                const ulonglong2 wa = *(const ulonglong2*)&Wsm4[(k0+dk)*64 + lane];
                const ulonglong2 wb = *(const ulonglong2*)&Wsm4[(k0+dk)*64 + 32 + lane];
                #pragma unroll
                for(int m=0;m<6;m++){
                    float hv = (dk==0)?h4[m].x:(dk==1)?h4[m].y:(dk==2)?h4[m].z:h4[m].w;
                    u64 hv2 = pkf(hv, hv);
                    if0[m] = fma2_(hv2, wa.x, if0[m]);
                    go0[m] = fma2_(hv2, wa.y, go0[m]);
                    if1[m] = fma2_(hv2, wb.x, if1[m]);
                    go1[m] = fma2_(hv2, wb.y, go1[m]);
                }
            }
        }
        __syncwarp();
        #pragma unroll
        for(int m=0;m<6;m++){
            float pi0, pf0, pg0, po0, pi1, pf1, pg1, po1;
            upk(if0[m], pi0, pf0); upk(go0[m], pg0, po0);
            upk(if1[m], pi1, pf1); upk(go1[m], pg1, po1);
            float i0=sigf(pi0), f0=sigf(pf0), g0=tanhf_(pg0), o0=sigf(po0);
            float i1=sigf(pi1), f1=sigf(pf1), g1=tanhf_(pg1), o1=sigf(po1);
            c0[m] = fmaf(f0, c0[m], i0*g0);
            c1[m] = fmaf(f1, c1[m], i1*g1);
            float h0 = o0*tanhf_(c0[m]);
            float h1 = o1*tanhf_(c1[m]);
            *(float2*)&hbase[m*64 + 2*lane] = make_float2(h0, h1);
        }
        __syncwarp();
    }
    float* agg = g_agg[et];
    #pragma unroll
    for(int m=0;m<6;m++){
        int n = nbase + m;
        if(n < NN){
            float2 hv = *(const float2*)&hbase[m*64 + 2*lane];
            ((float2*)(agg + n*64))[lane] = hv;
        }
    }
}

// ---- combine: 32 nodes/block, smem k-major weights; grid.y selects variant ----
__global__ void k_comb(const float* __restrict__ bl, int L,
                       int inSel, int outSel, int useRes){
    extern __shared__ float cs[];
    float* WlAT = cs;
    float* WlBT = cs + 4096;
    float* WrST = cs + 8192;
    float* A    = cs + 12288;
    float* B    = cs + 14336;
    float* X    = cs + 16384;
    float* blj  = cs + 18432;
    int v = blockIdx.y;          // 0: source side, 1: target side
    int ia = v ? (L*4+1) : (L*4+0);
    int ib = v ? (L*4+2) : (L*4+3);
    int etA = v ? 1 : 0;
    int etB = v ? 2 : 3;
    int isT = v;
    int tid = threadIdx.x;
    const float* wa = g_WlT + ia*4096;
    const float* wb = g_WlT + ib*4096;
    const float* ra = g_WrT + ia*4096;
    const float* rb = g_WrT + ib*4096;
    for(int i=tid;i<4096;i+=256){
        WlAT[i] = wa[i];
        WlBT[i] = wb[i];
        WrST[i] = ra[i] + rb[i];
    }
    if(tid < 64) blj[tid] = bl[ia*64+tid] + bl[ib*64+tid];
    int nb = blockIdx.x*32;
    const float* xin = isT ? g_tb[inSel] : g_sb[inSel];
    for(int i=tid;i<2048;i+=256){
        int node = nb + (i>>6); int c = i & 63;
        bool ok = node < NN;
        A[i] = ok ? g_agg[etA][node*64+c] : 0.0f;
        B[i] = ok ? g_agg[etB][node*64+c] : 0.0f;
        X[i] = ok ? xin[node*64+c] : 0.0f;
    }
    __syncthreads();
    int j = tid & 63, g = tid >> 6;
    float* out = isT ? g_tb[outSel] : g_sb[outSel];
    #pragma unroll
    for(int mi=0;mi<8;mi++){
        int m = g*8 + mi;
        int node = nb + m;
        float acc = blj[j];
        #pragma unroll 4
        for(int k=0;k<64;k++){
            acc = fmaf(A[m*64+k], WlAT[k*64+j], acc);
            acc = fmaf(B[m*64+k], WlBT[k*64+j], acc);
            acc = fmaf(X[m*64+k], WrST[k*64+j], acc);
        }
        acc *= 0.5f;
        if(useRes) acc += X[m*64+j];
        if(node < NN) out[node*64+j] = fmaxf(acc, 0.0f);
    }
}

// ---- edge head: 32 edges/block, smem k-major weights ----
__global__ void k_edge(const int* __restrict__ edges, const float* __restrict__ ea,
    const float* __restrict__ bg1, const float* __restrict__ Wg2, const float* __restrict__ bg2,
    const float* __restrict__ bm1, const float* __restrict__ bm2, const float* __restrict__ bm3,
    float* __restrict__ out){
    extern __shared__ float es[];
    float* Wg1T = es;               // 8192
    float* Wm1T = es + 8192;        // 5120
    float* Wm2T = es + 13312;       // 2048
    float* Wm3T = es + 15360;       // 64
    float* cvec = es + 15424;       // 256
    float* se   = es + 15680;       // 2048
    float* te   = es + 17728;       // 2048
    float* cat  = es + 19776;       // 2560
    float* h1   = es + 22336;       // 2048
    float* h2   = es + 24384;       // 1024
    float* red  = es + 25408;       // 64
    __shared__ int sidx[32], tidx[32];
    int tid = threadIdx.x;
    for(int i=tid;i<8192;i+=256) Wg1T[i] = g_Wg1T[i];
    for(int i=tid;i<5120;i+=256) Wm1T[i] = g_Wm1T[i];
    for(int i=tid;i<2048;i+=256) Wm2T[i] = g_Wm2T[i];
    if(tid < 64)  Wm3T[tid] = g_Wm3T[tid];
    if(tid < 64)  cvec[tid] = bg1[tid];
    else if(tid < 128) cvec[tid] = Wg2[tid-64];
    else if(tid < 192) cvec[tid] = bm1[tid-128];
    else if(tid < 224) cvec[tid] = bm2[tid-192];
    else if(tid == 224) cvec[224] = bm3[0];
    else if(tid == 225) cvec[225] = bm3[1];
    else if(tid == 226) cvec[226] = bg2[0];
    int ebase = blockIdx.x*32;
    if(tid < 32){
        sidx[tid] = edges[4*EE + ebase + tid];
        tidx[tid] = edges[5*EE + ebase + tid];
    }
    __syncthreads();
    for(int i=tid;i<2048;i+=256){
        int e = i >> 6, c = i & 63;
        se[i] = g_sb[1][sidx[e]*64 + c];
        te[i] = g_tb[1][tidx[e]*64 + c];
    }
    __syncthreads();
    int j = tid & 63, g = tid >> 6;
    int half = (tid >> 5) & 1;
    // Phase A: gate hidden dot Wg2, warp-reduced
    #pragma unroll
    for(int ei=0;ei<8;ei++){
        int e = g*8 + ei;
        float a = cvec[j];
        #pragma unroll 4
        for(int k=0;k<64;k++) a = fmaf(se[e*64+k], Wg1T[k*64+j], a);
        #pragma unroll 4
        for(int k=0;k<64;k++) a = fmaf(te[e*64+k], Wg1T[(64+k)*64+j], a);
        a = fmaxf(a, 0.0f);
        float v = a * cvec[64+j];
        #pragma unroll
        for(int off=16;off>0;off>>=1) v += __shfl_xor_sync(0xffffffffu, v, off);
        if((tid & 31) == 0) red[e*2 + half] = v;
    }
    __syncthreads();
    // Phase B: gate value, er || ea
    #pragma unroll
    for(int ei=0;ei<8;ei++){
        int e = g*8 + ei;
        float gv = sigf(red[e*2] + red[e*2+1] + cvec[226]);
        cat[e*80 + j] = gv*se[e*64+j] + (1.0f-gv)*te[e*64+j];
        if(j < 16) cat[e*80 + 64 + j] = ea[(ebase+e)*16 + j];
    }
    __syncthreads();
    // Phase C: m1
    #pragma unroll
    for(int ei=0;ei<8;ei++){
        int e = g*8 + ei;
        float m = cvec[128+j];
        #pragma unroll 4
        for(int k=0;k<80;k++) m = fmaf(cat[e*80+k], Wm1T[k*64+j], m);
        h1[e*64+j] = fmaxf(m, 0.0f);
    }
    __syncthreads();
    // Phase D: m2 (j<32)
    if(j < 32){
        #pragma unroll
        for(int ei=0;ei<8;ei++){
            int e = g*8 + ei;
            float m = cvec[192+j];
            #pragma unroll 4
            for(int k=0;k<64;k++) m = fmaf(h1[e*64+k], Wm2T[k*32+j], m);
            h2[e*32+j] = fmaxf(m, 0.0f);
        }
    }
    __syncthreads();
    // Phase E: m3 (j<2)
    if(j < 2){
        #pragma unroll
        for(int ei=0;ei<8;ei++){
            int e = g*8 + ei;
            float o = cvec[224+j];
            #pragma unroll
            for(int k=0;k<32;k++) o = fmaf(h2[e*32+k], Wm3T[k*2+j], o);
            out[(ebase+e)*2 + j] = o;
        }
    }
}

// ---------------- host launcher ----------------
extern "C" void kernel_launch(void* const* d_in, const int* in_sizes, int n_in,
                              void* d_out, int out_size){
    const float* x_source = (const float*)d_in[0];
    const float* x_target = (const float*)d_in[1];
    const int*   edges    = (const int*)  d_in[2];
    const float* ea       = (const float*)d_in[3];
    const float* We_s1=(const float*)d_in[4];  const float* be_s1=(const float*)d_in[5];
    const float* We_s2=(const float*)d_in[6];  const float* be_s2=(const float*)d_in[7];
    const float* We_t1=(const float*)d_in[8];  const float* be_t1=(const float*)d_in[9];
    const float* We_t2=(const float*)d_in[10]; const float* be_t2=(const float*)d_in[11];
    const float* Wih=(const float*)d_in[12];   const float* Whh=(const float*)d_in[13];
    const float* bih=(const float*)d_in[14];   const float* bhh=(const float*)d_in[15];
    const float* Wl =(const float*)d_in[16];   const float* bl =(const float*)d_in[17];
    const float* Wr =(const float*)d_in[18];
    const float* Wg1=(const float*)d_in[19];   const float* bg1=(const float*)d_in[20];
    const float* Wg2=(const float*)d_in[21];   const float* bg2=(const float*)d_in[22];
    const float* Wm1=(const float*)d_in[23];   const float* bm1=(const float*)d_in[24];
    const float* Wm2=(const float*)d_in[25];   const float* bm2=(const float*)d_in[26];
    const float* Wm3=(const float*)d_in[27];   const float* bm3=(const float*)d_in[28];
    float* out = (float*)d_out;

    cudaFuncSetAttribute(k_lstm, cudaFuncAttributeMaxDynamicSharedMemorySize, 77824);
    cudaFuncSetAttribute(k_comb, cudaFuncAttributeMaxDynamicSharedMemorySize, 75776);
    cudaFuncSetAttribute(k_edge, cudaFuncAttributeMaxDynamicSharedMemorySize, 102400);

    k_prep0   <<<(PREP0_TOTAL+255)/256, 256>>>(Whh, Wih, bih, bhh,
                                               Wl, Wr, Wg1, Wm1, Wm2, Wm3,
                                               We_s1, We_s2, We_t1, We_t2);
    k_degree  <<<(4*EE+255)/256, 256>>>(edges);
    k_scan    <<<4, 1024>>>();
    k_scatter <<<(4*EE+255)/256, 256>>>(edges);
    k_buildnbr<<<(4*NN+127)/128, 128>>>();
    k_enc     <<<dim3(313,2), 256>>>(x_source, x_target, be_s1, be_s2, be_t1, be_t2);

    for(int L=0; L<3; L++){
        int in = L & 1, o = 1 - in;
        k_U   <<<dim3(157,4), 256>>>(L, in);
        k_lstm<<<dim3(209,4), 256, 77824>>>(L);
        k_comb<<<dim3(313,2), 256, 75776>>>(bl, L, in, o, (L>0)?1:0);
    }
    k_edge<<<1250, 256, 102400>>>(edges, ea, bg1, Wg2, bg2, bm1, bm2, bm3, out);
}

// round 16
// speedup vs baseline: 1.0401x; 1.0008x over previous
#include <cuda_runtime.h>
#include <math.h>

#define NN 10000
#define HH 64
#define EE 40000
#define MD 12

typedef unsigned long long u64;
typedef unsigned int u32;

// ---------------- scratch (device globals; no allocation) ----------------
__device__ int   g_deg[4*NN];
__device__ int   g_start[4*NN];
__device__ int   g_cur[4*NN];
__device__ int   g_csr[4*EE];
__device__ int   g_nbr[4*NN*MD];
__device__ float g_sb[2][NN*HH];
__device__ float g_tb[2][NN*HH];
__device__ float g_agg[4][NN*HH];
__device__ float g_U[4][(NN+1)*256];
__device__ float g_Wp[12*64*256];     // permuted Whh: [blk][k][p]
__device__ float g_WihT[12*64*256];   // permuted Wih, k-major: [blk][k][p]
__device__ float g_bias2[12*256];     // bih+bhh, gate-permuted
// k-major transposed small weights
__device__ float g_WlT[12*64*64];
__device__ float g_WrT[12*64*64];
__device__ float g_Wg1T[128*64];
__device__ float g_Wm1T[80*64];
__device__ float g_Wm2T[64*32];
__device__ float g_Wm3T[32*2];
__device__ float g_E1sT[32*64];
__device__ float g_E2sT[64*64];
__device__ float g_E1tT[24*64];
__device__ float g_E2tT[64*64];

// gate-permuted index: p -> row of Wih/Whh (torch gate order i,f,g,o)
__device__ __forceinline__ int pmap_row(int p){
    return (p & 3) * 64 + 2 * ((p >> 2) & 31) + (p >> 7);
}
__device__ __forceinline__ float sigf(float x){
    return __fdividef(1.0f, 1.0f + __expf(-x));
}
__device__ __forceinline__ float tanhf_(float x){
    return fmaf(2.0f, __fdividef(1.0f, 1.0f + __expf(-2.0f*x)), -1.0f);
}

// ---------------- f32x2 packed helpers ----------------
__device__ __forceinline__ u64 pkf(float lo, float hi){
    u64 r; asm("mov.b64 %0, {%1,%2};" : "=l"(r) : "r"(__float_as_uint(lo)), "r"(__float_as_uint(hi))); return r;
}
__device__ __forceinline__ void upk(u64 v, float& lo, float& hi){
    u32 a, b;
    asm("mov.b64 {%0,%1}, %2;" : "=r"(a), "=r"(b) : "l"(v));
    lo = __uint_as_float(a); hi = __uint_as_float(b);
}
__device__ __forceinline__ u64 fma2_(u64 a, u64 b, u64 c){
    u64 d; asm("fma.rn.f32x2 %0, %1, %2, %3;" : "=l"(d) : "l"(a), "l"(b), "l"(c)); return d;
}

// ---------------- graph preprocessing ----------------
// mega-prep: zero counters + Whh perm + Wih perm (k-major) + bias + all
// small-weight transposes. All sections independent.
__global__ void k_prep0(const float* __restrict__ Whh, const float* __restrict__ Wih,
                        const float* __restrict__ bih, const float* __restrict__ bhh,
                        const float* __restrict__ Wl, const float* __restrict__ Wr,
                        const float* __restrict__ Wg1, const float* __restrict__ Wm1,
                        const float* __restrict__ Wm2, const float* __restrict__ Wm3,
                        const float* __restrict__ E1s, const float* __restrict__ E2s,
                        const float* __restrict__ E1t, const float* __restrict__ E2t){
    int idx = blockIdx.x*blockDim.x + threadIdx.x;
    if(idx < 4*NN){ g_deg[idx] = 0; g_cur[idx] = 0; return; }
    idx -= 4*NN;
    if(idx < 12*16384){
        int i = idx >> 14; int r = idx & 16383; int k = r >> 8; int p = r & 255;
        g_Wp[idx] = Whh[i*16384 + pmap_row(p)*64 + k];
        return;
    }
    idx -= 12*16384;
    if(idx < 12*16384){
        int i = idx >> 14; int r = idx & 16383; int k = r >> 8; int p = r & 255;
        g_WihT[idx] = Wih[i*16384 + pmap_row(p)*64 + k];
        return;
    }
    idx -= 12*16384;
    if(idx < 12*256){
        int i = idx >> 8; int p = idx & 255; int row = pmap_row(p);
        g_bias2[idx] = bih[i*256 + row] + bhh[i*256 + row];
        return;
    }
    idx -= 12*256;
    if(idx < 49152){ int i=idx/4096, r=idx%4096, k=r/64, j=r%64; g_WlT[idx] = Wl[i*4096 + j*64 + k]; return; }
    idx -= 49152;
    if(idx < 49152){ int i=idx/4096, r=idx%4096, k=r/64, j=r%64; g_WrT[idx] = Wr[i*4096 + j*64 + k]; return; }
    idx -= 49152;
    if(idx < 8192){ int k=idx/64, j=idx%64; g_Wg1T[idx] = Wg1[j*128 + k]; return; }
    idx -= 8192;
    if(idx < 5120){ int k=idx/64, j=idx%64; g_Wm1T[idx] = Wm1[j*80 + k]; return; }
    idx -= 5120;
    if(idx < 2048){ int k=idx/32, j=idx%32; g_Wm2T[idx] = Wm2[j*64 + k]; return; }
    idx -= 2048;
    if(idx < 64){ int k=idx/2, j=idx%2; g_Wm3T[idx] = Wm3[j*32 + k]; return; }
    idx -= 64;
    if(idx < 2048){ int k=idx/64, j=idx%64; g_E1sT[idx] = E1s[j*32 + k]; return; }
    idx -= 2048;
    if(idx < 4096){ int k=idx/64, j=idx%64; g_E2sT[idx] = E2s[j*64 + k]; return; }
    idx -= 4096;
    if(idx < 1536){ int k=idx/64, j=idx%64; g_E1tT[idx] = E1t[j*24 + k]; return; }
    idx -= 1536;
    if(idx < 4096){ int k=idx/64, j=idx%64; g_E2tT[idx] = E2t[j*64 + k]; return; }
}
#define PREP0_TOTAL (4*NN + 2*12*16384 + 12*256 + 49152+49152+8192+5120+2048+64+2048+4096+1536+4096)

__global__ void k_degree(const int* __restrict__ edges){
    int i = blockIdx.x*blockDim.x + threadIdx.x;
    if(i >= 4*EE) return;
    int t = i / EE, e = i - t*EE;
    int dst = edges[t*2*EE + EE + e];
    atomicAdd(&g_deg[t*NN + dst], 1);
}

__global__ void k_scan(){
    __shared__ int sm[1024];
    int t = blockIdx.x, tid = threadIdx.x;
    const int CH = 10;
    int loc[CH]; int s = 0;
    int base = tid * CH;
    #pragma unroll
    for(int c=0;c<CH;c++){ int i = base + c; int v = (i<NN) ? g_deg[t*NN+i] : 0; loc[c] = v; s += v; }
    sm[tid] = s; __syncthreads();
    for(int off=1; off<1024; off<<=1){
        int v = (tid >= off) ? sm[tid-off] : 0;
        __syncthreads();
        sm[tid] += v;
        __syncthreads();
    }
    int run = sm[tid] - s;
    #pragma unroll
    for(int c=0;c<CH;c++){ int i = base + c; if(i < NN){ g_start[t*NN+i] = run; run += loc[c]; } }
}

__global__ void k_scatter(const int* __restrict__ edges){
    int i = blockIdx.x*blockDim.x + threadIdx.x;
    if(i >= 4*EE) return;
    int t = i / EE, e = i - t*EE;
    int src = edges[t*2*EE + e];
    int dst = edges[t*2*EE + EE + e];
    int p = atomicAdd(&g_cur[t*NN + dst], 1);
    g_csr[t*EE + g_start[t*NN + dst] + p] = src;
}

// top-12 smallest src per dst (incl. self loop), pad with sentinel NN
__global__ void k_buildnbr(){
    int i = blockIdx.x*blockDim.x + threadIdx.x;
    if(i >= 4*NN) return;
    int t = i / NN, n = i - t*NN;
    int arr[MD];
    #pragma unroll
    for(int k=0;k<MD;k++) arr[k] = 0x7fffffff;
    arr[0] = n;
    int st = g_start[t*NN + n], d = g_deg[t*NN + n];
    for(int q=0;q<d;q++){
        int v = g_csr[t*EE + st + q];
        if(v < arr[MD-1]){
            int j = MD-1;
            while(j > 0 && arr[j-1] > v){ arr[j] = arr[j-1]; j--; }
            arr[j] = v;
        }
    }
    int cnt = d + 1; if(cnt > MD) cnt = MD;
    #pragma unroll
    for(int k=0;k<MD;k++) g_nbr[i*MD + k] = (k < cnt) ? arr[k] : NN;
}

// ---------------- node encoder: 32 nodes/block, both types via grid.y ----
__global__ void k_enc(const float* __restrict__ xs, const float* __restrict__ xt,
                      const float* __restrict__ b1s_, const float* __restrict__ b2s_,
                      const float* __restrict__ b1t_, const float* __restrict__ b2t_){
    __shared__ float W1T[32*64];
    __shared__ float W2T[64*64];
    __shared__ float xin[32*32];
    __shared__ float hid[32*64];
    __shared__ float b1s[64], b2s[64];
    int isT = blockIdx.y;
    int K = isT ? 24 : 32;
    const float* x  = isT ? xt : xs;
    const float* b1 = isT ? b1t_ : b1s_;
    const float* b2 = isT ? b2t_ : b2s_;
    int tid = threadIdx.x;
    const float* w1src = isT ? g_E1tT : g_E1sT;
    const float* w2src = isT ? g_E2tT : g_E2sT;
    for(int i=tid;i<K*64;i+=256) W1T[i] = w1src[i];
    for(int i=tid;i<4096;i+=256) W2T[i] = w2src[i];
    if(tid < 64){ b1s[tid] = b1[tid]; b2s[tid] = b2[tid]; }
    int nb = blockIdx.x*32;
    for(int i=tid;i<32*K;i+=256){
        int node = nb + i/K;
        xin[i] = (node < NN) ? x[node*K + (i%K)] : 0.0f;
    }
    __syncthreads();
    int j = tid & 63, g = tid >> 6;
    #pragma unroll
    for(int mi=0;mi<8;mi++){
        int m = g*8 + mi;
        float a = b1s[j];
        for(int k=0;k<K;k++) a = fmaf(xin[m*K+k], W1T[k*64+j], a);
        hid[m*64+j] = fmaxf(a, 0.0f);
    }
    __syncthreads();
    float* out = isT ? g_tb[0] : g_sb[0];
    #pragma unroll
    for(int mi=0;mi<8;mi++){
        int m = g*8 + mi;
        int node = nb + m;
        float a = b2s[j];
        #pragma unroll 8
        for(int k=0;k<64;k++) a = fmaf(hid[m*64+k], W2T[k*64+j], a);
        if(node < NN) out[node*64+j] = a;
    }
}

// ---- U = X @ Wih^T + bias (gate-permuted); W column register-resident ----
__global__ void k_U(int L, int inSel){
    int et = blockIdx.y;
    int blk = L*4 + et;
    int isT = (et==1 || et==3);
    const float* x = isT ? g_tb[inSel] : g_sb[inSel];
    float* U = g_U[et];
    __shared__ float4 xsm[64*16];
    int p = threadIdx.x;
    float w[64];
    const float* wt = g_WihT + (size_t)blk*16384;
    #pragma unroll
    for(int k=0;k<64;k++) w[k] = wt[k*256 + p];
    float bias = g_bias2[blk*256 + p];
    int nb = blockIdx.x * 64;
    #pragma unroll
    for(int r=0;r<4;r++){
        int idx = p + r*256;
        int node = nb + (idx >> 4);
        float4 v = make_float4(0,0,0,0);
        if(node < NN) v = ((const float4*)x)[node*16 + (idx & 15)];
        xsm[idx] = v;
    }
    __syncthreads();
    for(int m=0;m<64;m++){
        int node = nb + m;
        if(node > NN) break;
        float acc = bias;
        #pragma unroll
        for(int q=0;q<16;q++){
            float4 xv = xsm[m*16 + q];
            acc = fmaf(xv.x, w[4*q+0], acc);
            acc = fmaf(xv.y, w[4*q+1], acc);
            acc = fmaf(xv.z, w[4*q+2], acc);
            acc = fmaf(xv.w, w[4*q+3], acc);
        }
        U[node*256 + p] = acc;
    }
}

// ---------------- LSTM aggregation (hot kernel, best: 6 nodes/warp) ----
__global__ void __launch_bounds__(256, 2) k_lstm(int L){
    extern __shared__ float smem[];
    float4* Wsm4 = (float4*)smem;            // 64KB
    float*  hsm  = smem + 16384;             // 48*64 = 12KB
    int et = blockIdx.y;
    int blk = L*4 + et;
    int tid = threadIdx.x;
    const float4* wp = (const float4*)(g_Wp + (size_t)blk*16384);
    #pragma unroll
    for(int r=0;r<16;r++) Wsm4[tid + r*256] = wp[tid + r*256];
    #pragma unroll
    for(int r=0;r<12;r++) hsm[tid + r*256] = 0.0f;
    __syncthreads();

    int warp = tid>>5, lane = tid&31;
    int nbase = blockIdx.x*48 + warp*6;
    const int* nbr = g_nbr + et*NN*MD;
    const float4* U4 = (const float4*)g_U[et];
    float c0[6], c1[6];
    int nodes[6];
    #pragma unroll
    for(int m=0;m<6;m++){
        c0[m]=0.f; c1[m]=0.f;
        int n = nbase+m; nodes[m] = (n<NN)?n:(NN-1);
    }
    float* hbase = hsm + warp*6*64;

    for(int t=0;t<MD;t++){
        u64 if0[6], go0[6], if1[6], go1[6];
        #pragma unroll
        for(int m=0;m<6;m++){
            int nb = __ldg(&nbr[nodes[m]*MD + t]);
            float4 a0 = __ldg(&U4[nb*64 + lane]);
            float4 a1 = __ldg(&U4[nb*64 + 32 + lane]);
            if0[m] = pkf(a0.x, a0.y); go0[m] = pkf(a0.z, a0.w);
            if1[m] = pkf(a1.x, a1.y); go1[m] = pkf(a1.z, a1.w);
        }
        #pragma unroll
        for(int k0=0;k0<64;k0+=4){
            float4 h4[6];
            #pragma unroll
            for(int m=0;m<6;m++) h4[m] = *(const float4*)&hbase[m*64 + k0];
            #pragma unroll
            for(int dk=0;dk<4;dk++){
                const ulonglong2 wa = *(const ulonglong2*)&Wsm4[(k0+dk)*64 + lane];
                const ulonglong2 wb = *(const ulonglong2*)&Wsm4[(k0+dk)*64 + 32 + lane];
                #pragma unroll
                for(int m=0;m<6;m++){
                    float hv = (dk==0)?h4[m].x:(dk==1)?h4[m].y:(dk==2)?h4[m].z:h4[m].w;
                    u64 hv2 = pkf(hv, hv);
                    if0[m] = fma2_(hv2, wa.x, if0[m]);
                    go0[m] = fma2_(hv2, wa.y, go0[m]);
                    if1[m] = fma2_(hv2, wb.x, if1[m]);
                    go1[m] = fma2_(hv2, wb.y, go1[m]);
                }
            }
        }
        __syncwarp();
        #pragma unroll
        for(int m=0;m<6;m++){
            float pi0, pf0, pg0, po0, pi1, pf1, pg1, po1;
            upk(if0[m], pi0, pf0); upk(go0[m], pg0, po0);
            upk(if1[m], pi1, pf1); upk(go1[m], pg1, po1);
            float i0=sigf(pi0), f0=sigf(pf0), g0=tanhf_(pg0), o0=sigf(po0);
            float i1=sigf(pi1), f1=sigf(pf1), g1=tanhf_(pg1), o1=sigf(po1);
            c0[m] = fmaf(f0, c0[m], i0*g0);
            c1[m] = fmaf(f1, c1[m], i1*g1);
            float h0 = o0*tanhf_(c0[m]);
            float h1 = o1*tanhf_(c1[m]);
            *(float2*)&hbase[m*64 + 2*lane] = make_float2(h0, h1);
        }
        __syncwarp();
    }
    float* agg = g_agg[et];
    #pragma unroll
    for(int m=0;m<6;m++){
        int n = nbase + m;
        if(n < NN){
            float2 hv = *(const float2*)&hbase[m*64 + 2*lane];
            ((float2*)(agg + n*64))[lane] = hv;
        }
    }
}

// ---- combine: 32 nodes/block, smem k-major weights; grid.y selects variant ----
__global__ void k_comb(const float* __restrict__ bl, int L,
                       int inSel, int outSel, int useRes){
    extern __shared__ float cs[];
    float* WlAT = cs;
    float* WlBT = cs + 4096;
    float* WrST = cs + 8192;
    float* A    = cs + 12288;
    float* B    = cs + 14336;
    float* X    = cs + 16384;
    float* blj  = cs + 18432;
    int v = blockIdx.y;          // 0: source side, 1: target side
    int ia = v ? (L*4+1) : (L*4+0);
    int ib = v ? (L*4+2) : (L*4+3);
    int etA = v ? 1 : 0;
    int etB = v ? 2 : 3;
    int isT = v;
    int tid = threadIdx.x;
    const float* wa = g_WlT + ia*4096;
    const float* wb = g_WlT + ib*4096;
    const float* ra = g_WrT + ia*4096;
    const float* rb = g_WrT + ib*4096;
    for(int i=tid;i<4096;i+=256){
        WlAT[i] = wa[i];
        WlBT[i] = wb[i];
        WrST[i] = ra[i] + rb[i];
    }
    if(tid < 64) blj[tid] = bl[ia*64+tid] + bl[ib*64+tid];
    int nb = blockIdx.x*32;
    const float* xin = isT ? g_tb[inSel] : g_sb[inSel];
    for(int i=tid;i<2048;i+=256){
        int node = nb + (i>>6); int c = i & 63;
        bool ok = node < NN;
        A[i] = ok ? g_agg[etA][node*64+c] : 0.0f;
        B[i] = ok ? g_agg[etB][node*64+c] : 0.0f;
        X[i] = ok ? xin[node*64+c] : 0.0f;
    }
    __syncthreads();
    int j = tid & 63, g = tid >> 6;
    float* out = isT ? g_tb[outSel] : g_sb[outSel];
    #pragma unroll
    for(int mi=0;mi<8;mi++){
        int m = g*8 + mi;
        int node = nb + m;
        float acc = blj[j];
        #pragma unroll 4
        for(int k=0;k<64;k++){
            acc = fmaf(A[m*64+k], WlAT[k*64+j], acc);
            acc = fmaf(B[m*64+k], WlBT[k*64+j], acc);
            acc = fmaf(X[m*64+k], WrST[k*64+j], acc);
        }
        acc *= 0.5f;
        if(useRes) acc += X[m*64+j];
        if(node < NN) out[node*64+j] = fmaxf(acc, 0.0f);
    }
}

// ---- edge head: 32 edges/block, smem k-major weights ----
__global__ void k_edge(const int* __restrict__ edges, const float* __restrict__ ea,
    const float* __restrict__ bg1, const float* __restrict__ Wg2, const float* __restrict__ bg2,
    const float* __restrict__ bm1, const float* __restrict__ bm2, const float* __restrict__ bm3,
    float* __restrict__ out){
    extern __shared__ float es[];
    float* Wg1T = es;               // 8192
    float* Wm1T = es + 8192;        // 5120
    float* Wm2T = es + 13312;       // 2048
    float* Wm3T = es + 15360;       // 64
    float* cvec = es + 15424;       // 256
    float* se   = es + 15680;       // 2048
    float* te   = es + 17728;       // 2048
    float* cat  = es + 19776;       // 2560
    float* h1   = es + 22336;       // 2048
    float* h2   = es + 24384;       // 1024
    float* red  = es + 25408;       // 64
    __shared__ int sidx[32], tidx[32];
    int tid = threadIdx.x;
    for(int i=tid;i<8192;i+=256) Wg1T[i] = g_Wg1T[i];
    for(int i=tid;i<5120;i+=256) Wm1T[i] = g_Wm1T[i];
    for(int i=tid;i<2048;i+=256) Wm2T[i] = g_Wm2T[i];
    if(tid < 64)  Wm3T[tid] = g_Wm3T[tid];
    if(tid < 64)  cvec[tid] = bg1[tid];
    else if(tid < 128) cvec[tid] = Wg2[tid-64];
    else if(tid < 192) cvec[tid] = bm1[tid-128];
    else if(tid < 224) cvec[tid] = bm2[tid-192];
    else if(tid == 224) cvec[224] = bm3[0];
    else if(tid == 225) cvec[225] = bm3[1];
    else if(tid == 226) cvec[226] = bg2[0];
    int ebase = blockIdx.x*32;
    if(tid < 32){
        sidx[tid] = edges[4*EE + ebase + tid];
        tidx[tid] = edges[5*EE + ebase + tid];
    }
    __syncthreads();
    for(int i=tid;i<2048;i+=256){
        int e = i >> 6, c = i & 63;
        se[i] = g_sb[1][sidx[e]*64 + c];
        te[i] = g_tb[1][tidx[e]*64 + c];
    }
    __syncthreads();
    int j = tid & 63, g = tid >> 6;
    int half = (tid >> 5) & 1;
    // Phase A: gate hidden dot Wg2, warp-reduced
    #pragma unroll
    for(int ei=0;ei<8;ei++){
        int e = g*8 + ei;
        float a = cvec[j];
        #pragma unroll 4
        for(int k=0;k<64;k++) a = fmaf(se[e*64+k], Wg1T[k*64+j], a);
        #pragma unroll 4
        for(int k=0;k<64;k++) a = fmaf(te[e*64+k], Wg1T[(64+k)*64+j], a);
        a = fmaxf(a, 0.0f);
        float v = a * cvec[64+j];
        #pragma unroll
        for(int off=16;off>0;off>>=1) v += __shfl_xor_sync(0xffffffffu, v, off);
        if((tid & 31) == 0) red[e*2 + half] = v;
    }
    __syncthreads();
    // Phase B: gate value, er || ea
    #pragma unroll
    for(int ei=0;ei<8;ei++){
        int e = g*8 + ei;
        float gv = sigf(red[e*2] + red[e*2+1] + cvec[226]);
        cat[e*80 + j] = gv*se[e*64+j] + (1.0f-gv)*te[e*64+j];
        if(j < 16) cat[e*80 + 64 + j] = ea[(ebase+e)*16 + j];
    }
    __syncthreads();
    // Phase C: m1
    #pragma unroll
    for(int ei=0;ei<8;ei++){
        int e = g*8 + ei;
        float m = cvec[128+j];
        #pragma unroll 4
        for(int k=0;k<80;k++) m = fmaf(cat[e*80+k], Wm1T[k*64+j], m);
        h1[e*64+j] = fmaxf(m, 0.0f);
    }
    __syncthreads();
    // Phase D: m2 (j<32)
    if(j < 32){
        #pragma unroll
        for(int ei=0;ei<8;ei++){
            int e = g*8 + ei;
            float m = cvec[192+j];
            #pragma unroll 4
            for(int k=0;k<64;k++) m = fmaf(h1[e*64+k], Wm2T[k*32+j], m);
            h2[e*32+j] = fmaxf(m, 0.0f);
        }
    }
    __syncthreads();
    // Phase E: m3 (j<2)
    if(j < 2){
        #pragma unroll
        for(int ei=0;ei<8;ei++){
            int e = g*8 + ei;
            float o = cvec[224+j];
            #pragma unroll
            for(int k=0;k<32;k++) o = fmaf(h2[e*32+k], Wm3T[k*2+j], o);
            out[(ebase+e)*2 + j] = o;
        }
    }
}

// ---------------- host launcher ----------------
extern "C" void kernel_launch(void* const* d_in, const int* in_sizes, int n_in,
                              void* d_out, int out_size){
    const float* x_source = (const float*)d_in[0];
    const float* x_target = (const float*)d_in[1];
    const int*   edges    = (const int*)  d_in[2];
    const float* ea       = (const float*)d_in[3];
    const float* We_s1=(const float*)d_in[4];  const float* be_s1=(const float*)d_in[5];
    const float* We_s2=(const float*)d_in[6];  const float* be_s2=(const float*)d_in[7];
    const float* We_t1=(const float*)d_in[8];  const float* be_t1=(const float*)d_in[9];
    const float* We_t2=(const float*)d_in[10]; const float* be_t2=(const float*)d_in[11];
    const float* Wih=(const float*)d_in[12];   const float* Whh=(const float*)d_in[13];
    const float* bih=(const float*)d_in[14];   const float* bhh=(const float*)d_in[15];
    const float* Wl =(const float*)d_in[16];   const float* bl =(const float*)d_in[17];
    const float* Wr =(const float*)d_in[18];
    const float* Wg1=(const float*)d_in[19];   const float* bg1=(const float*)d_in[20];
    const float* Wg2=(const float*)d_in[21];   const float* bg2=(const float*)d_in[22];
    const float* Wm1=(const float*)d_in[23];   const float* bm1=(const float*)d_in[24];
    const float* Wm2=(const float*)d_in[25];   const float* bm2=(const float*)d_in[26];
    const float* Wm3=(const float*)d_in[27];   const float* bm3=(const float*)d_in[28];
    float* out = (float*)d_out;

    cudaFuncSetAttribute(k_lstm, cudaFuncAttributeMaxDynamicSharedMemorySize, 77824);
    cudaFuncSetAttribute(k_comb, cudaFuncAttributeMaxDynamicSharedMemorySize, 75776);
    cudaFuncSetAttribute(k_edge, cudaFuncAttributeMaxDynamicSharedMemorySize, 102400);

    k_prep0   <<<(PREP0_TOTAL+255)/256, 256>>>(Whh, Wih, bih, bhh,
                                               Wl, Wr, Wg1, Wm1, Wm2, Wm3,
                                               We_s1, We_s2, We_t1, We_t2);
    k_degree  <<<(4*EE+255)/256, 256>>>(edges);
    k_scan    <<<4, 1024>>>();
    k_scatter <<<(4*EE+255)/256, 256>>>(edges);
    k_buildnbr<<<(4*NN+127)/128, 128>>>();
    k_enc     <<<dim3(313,2), 256>>>(x_source, x_target, be_s1, be_s2, be_t1, be_t2);

    for(int L=0; L<3; L++){
        int in = L & 1, o = 1 - in;
        k_U   <<<dim3(157,4), 256>>>(L, in);
        k_lstm<<<dim3(209,4), 256, 77824>>>(L);
        k_comb<<<dim3(313,2), 256, 75776>>>(bl, L, in, o, (L>0)?1:0);
    }
    k_edge<<<1250, 256, 102400>>>(edges, ea, bg1, Wg2, bg2, bm1, bm2, bm3, out);
}

// round 17
// speedup vs baseline: 1.0409x; 1.0008x over previous
#include <cuda_runtime.h>
#include <math.h>

#define NN 10000
#define HH 64
#define EE 40000
#define MD 12

typedef unsigned long long u64;
typedef unsigned int u32;

// ---------------- scratch (device globals; no allocation) ----------------
__device__ int   g_deg[4*NN];
__device__ int   g_start[4*NN];
__device__ int   g_cur[4*NN];
__device__ int   g_csr[4*EE];
__device__ int   g_nbr[4*NN*MD];
__device__ float g_sb[2][NN*HH];
__device__ float g_tb[2][NN*HH];
__device__ float g_agg[4][NN*HH];
__device__ float g_U[4][(NN+1)*256];
__device__ float g_Wp[12*64*256];     // permuted Whh: [blk][k][p]
__device__ float g_WihT[12*64*256];   // permuted Wih, k-major: [blk][k][p]
__device__ float g_bias2[12*256];     // bih+bhh, gate-permuted
// k-major transposed small weights
__device__ float g_WlT[12*64*64];
__device__ float g_WrT[12*64*64];
__device__ float g_Wg1T[128*64];
__device__ float g_Wm1T[80*64];
__device__ float g_Wm2T[64*32];
__device__ float g_Wm3T[32*2];
__device__ float g_E1sT[32*64];
__device__ float g_E2sT[64*64];
__device__ float g_E1tT[24*64];
__device__ float g_E2tT[64*64];

// gate-permuted index: p -> row of Wih/Whh (torch gate order i,f,g,o)
__device__ __forceinline__ int pmap_row(int p){
    return (p & 3) * 64 + 2 * ((p >> 2) & 31) + (p >> 7);
}
__device__ __forceinline__ float sigf(float x){
    return __fdividef(1.0f, 1.0f + __expf(-x));
}
__device__ __forceinline__ float tanhf_(float x){
    return fmaf(2.0f, __fdividef(1.0f, 1.0f + __expf(-2.0f*x)), -1.0f);
}

// ---------------- f32x2 packed helpers ----------------
__device__ __forceinline__ u64 pkf(float lo, float hi){
    u64 r; asm("mov.b64 %0, {%1,%2};" : "=l"(r) : "r"(__float_as_uint(lo)), "r"(__float_as_uint(hi))); return r;
}
__device__ __forceinline__ void upk(u64 v, float& lo, float& hi){
    u32 a, b;
    asm("mov.b64 {%0,%1}, %2;" : "=r"(a), "=r"(b) : "l"(v));
    lo = __uint_as_float(a); hi = __uint_as_float(b);
}
__device__ __forceinline__ u64 fma2_(u64 a, u64 b, u64 c){
    u64 d; asm("fma.rn.f32x2 %0, %1, %2, %3;" : "=l"(d) : "l"(a), "l"(b), "l"(c)); return d;
}

// ---------------- graph preprocessing ----------------
// mega-prep: zero counters + Whh perm + Wih perm (k-major) + bias + all
// small-weight transposes. All sections independent.
__global__ void k_prep0(const float* __restrict__ Whh, const float* __restrict__ Wih,
                        const float* __restrict__ bih, const float* __restrict__ bhh,
                        const float* __restrict__ Wl, const float* __restrict__ Wr,
                        const float* __restrict__ Wg1, const float* __restrict__ Wm1,
                        const float* __restrict__ Wm2, const float* __restrict__ Wm3,
                        const float* __restrict__ E1s, const float* __restrict__ E2s,
                        const float* __restrict__ E1t, const float* __restrict__ E2t){
    int idx = blockIdx.x*blockDim.x + threadIdx.x;
    if(idx < 4*NN){ g_deg[idx] = 0; g_cur[idx] = 0; return; }
    idx -= 4*NN;
    if(idx < 12*16384){
        int i = idx >> 14; int r = idx & 16383; int k = r >> 8; int p = r & 255;
        g_Wp[idx] = Whh[i*16384 + pmap_row(p)*64 + k];
        return;
    }
    idx -= 12*16384;
    if(idx < 12*16384){
        int i = idx >> 14; int r = idx & 16383; int k = r >> 8; int p = r & 255;
        g_WihT[idx] = Wih[i*16384 + pmap_row(p)*64 + k];
        return;
    }
    idx -= 12*16384;
    if(idx < 12*256){
        int i = idx >> 8; int p = idx & 255; int row = pmap_row(p);
        g_bias2[idx] = bih[i*256 + row] + bhh[i*256 + row];
        return;
    }
    idx -= 12*256;
    if(idx < 49152){ int i=idx/4096, r=idx%4096, k=r/64, j=r%64; g_WlT[idx] = Wl[i*4096 + j*64 + k]; return; }
    idx -= 49152;
    if(idx < 49152){ int i=idx/4096, r=idx%4096, k=r/64, j=r%64; g_WrT[idx] = Wr[i*4096 + j*64 + k]; return; }
    idx -= 49152;
    if(idx < 8192){ int k=idx/64, j=idx%64; g_Wg1T[idx] = Wg1[j*128 + k]; return; }
    idx -= 8192;
    if(idx < 5120){ int k=idx/64, j=idx%64; g_Wm1T[idx] = Wm1[j*80 + k]; return; }
    idx -= 5120;
    if(idx < 2048){ int k=idx/32, j=idx%32; g_Wm2T[idx] = Wm2[j*64 + k]; return; }
    idx -= 2048;
    if(idx < 64){ int k=idx/2, j=idx%2; g_Wm3T[idx] = Wm3[j*32 + k]; return; }
    idx -= 64;
    if(idx < 2048){ int k=idx/64, j=idx%64; g_E1sT[idx] = E1s[j*32 + k]; return; }
    idx -= 2048;
    if(idx < 4096){ int k=idx/64, j=idx%64; g_E2sT[idx] = E2s[j*64 + k]; return; }
    idx -= 4096;
    if(idx < 1536){ int k=idx/64, j=idx%64; g_E1tT[idx] = E1t[j*24 + k]; return; }
    idx -= 1536;
    if(idx < 4096){ int k=idx/64, j=idx%64; g_E2tT[idx] = E2t[j*64 + k]; return; }
}
#define PREP0_TOTAL (4*NN + 2*12*16384 + 12*256 + 49152+49152+8192+5120+2048+64+2048+4096+1536+4096)

__global__ void k_degree(const int* __restrict__ edges){
    int i = blockIdx.x*blockDim.x + threadIdx.x;
    if(i >= 4*EE) return;
    int t = i / EE, e = i - t*EE;
    int dst = edges[t*2*EE + EE + e];
    atomicAdd(&g_deg[t*NN + dst], 1);
}

__global__ void k_scan(){
    __shared__ int sm[1024];
    int t = blockIdx.x, tid = threadIdx.x;
    const int CH = 10;
    int loc[CH]; int s = 0;
    int base = tid * CH;
    #pragma unroll
    for(int c=0;c<CH;c++){ int i = base + c; int v = (i<NN) ? g_deg[t*NN+i] : 0; loc[c] = v; s += v; }
    sm[tid] = s; __syncthreads();
    for(int off=1; off<1024; off<<=1){
        int v = (tid >= off) ? sm[tid-off] : 0;
        __syncthreads();
        sm[tid] += v;
        __syncthreads();
    }
    int run = sm[tid] - s;
    #pragma unroll
    for(int c=0;c<CH;c++){ int i = base + c; if(i < NN){ g_start[t*NN+i] = run; run += loc[c]; } }
}

__global__ void k_scatter(const int* __restrict__ edges){
    int i = blockIdx.x*blockDim.x + threadIdx.x;
    if(i >= 4*EE) return;
    int t = i / EE, e = i - t*EE;
    int src = edges[t*2*EE + e];
    int dst = edges[t*2*EE + EE + e];
    int p = atomicAdd(&g_cur[t*NN + dst], 1);
    g_csr[t*EE + g_start[t*NN + dst] + p] = src;
}

// top-12 smallest src per dst (incl. self loop), pad with sentinel NN
__global__ void k_buildnbr(){
    int i = blockIdx.x*blockDim.x + threadIdx.x;
    if(i >= 4*NN) return;
    int t = i / NN, n = i - t*NN;
    int arr[MD];
    #pragma unroll
    for(int k=0;k<MD;k++) arr[k] = 0x7fffffff;
    arr[0] = n;
    int st = g_start[t*NN + n], d = g_deg[t*NN + n];
    for(int q=0;q<d;q++){
        int v = g_csr[t*EE + st + q];
        if(v < arr[MD-1]){
            int j = MD-1;
            while(j > 0 && arr[j-1] > v){ arr[j] = arr[j-1]; j--; }
            arr[j] = v;
        }
    }
    int cnt = d + 1; if(cnt > MD) cnt = MD;
    #pragma unroll
    for(int k=0;k<MD;k++) g_nbr[i*MD + k] = (k < cnt) ? arr[k] : NN;
}

// ---------------- node encoder: 32 nodes/block, both types via grid.y ----
__global__ void k_enc(const float* __restrict__ xs, const float* __restrict__ xt,
                      const float* __restrict__ b1s_, const float* __restrict__ b2s_,
                      const float* __restrict__ b1t_, const float* __restrict__ b2t_){
    __shared__ float W1T[32*64];
    __shared__ float W2T[64*64];
    __shared__ float xin[32*32];
    __shared__ float hid[32*64];
    __shared__ float b1s[64], b2s[64];
    int isT = blockIdx.y;
    int K = isT ? 24 : 32;
    const float* x  = isT ? xt : xs;
    const float* b1 = isT ? b1t_ : b1s_;
    const float* b2 = isT ? b2t_ : b2s_;
    int tid = threadIdx.x;
    const float* w1src = isT ? g_E1tT : g_E1sT;
    const float* w2src = isT ? g_E2tT : g_E2sT;
    for(int i=tid;i<K*64;i+=256) W1T[i] = w1src[i];
    for(int i=tid;i<4096;i+=256) W2T[i] = w2src[i];
    if(tid < 64){ b1s[tid] = b1[tid]; b2s[tid] = b2[tid]; }
    int nb = blockIdx.x*32;
    for(int i=tid;i<32*K;i+=256){
        int node = nb + i/K;
        xin[i] = (node < NN) ? x[node*K + (i%K)] : 0.0f;
    }
    __syncthreads();
    int j = tid & 63, g = tid >> 6;
    #pragma unroll
    for(int mi=0;mi<8;mi++){
        int m = g*8 + mi;
        float a = b1s[j];
        for(int k=0;k<K;k++) a = fmaf(xin[m*K+k], W1T[k*64+j], a);
        hid[m*64+j] = fmaxf(a, 0.0f);
    }
    __syncthreads();
    float* out = isT ? g_tb[0] : g_sb[0];
    #pragma unroll
    for(int mi=0;mi<8;mi++){
        int m = g*8 + mi;
        int node = nb + m;
        float a = b2s[j];
        #pragma unroll 8
        for(int k=0;k<64;k++) a = fmaf(hid[m*64+k], W2T[k*64+j], a);
        if(node < NN) out[node*64+j] = a;
    }
}

// ---- U = X @ Wih^T + bias (gate-permuted); W column register-resident ----
__global__ void k_U(int L, int inSel){
    int et = blockIdx.y;
    int blk = L*4 + et;
    int isT = (et==1 || et==3);
    const float* x = isT ? g_tb[inSel] : g_sb[inSel];
    float* U = g_U[et];
    __shared__ float4 xsm[64*16];
    int p = threadIdx.x;
    float w[64];
    const float* wt = g_WihT + (size_t)blk*16384;
    #pragma unroll
    for(int k=0;k<64;k++) w[k] = wt[k*256 + p];
    float bias = g_bias2[blk*256 + p];
    int nb = blockIdx.x * 64;
    #pragma unroll
    for(int r=0;r<4;r++){
        int idx = p + r*256;
        int node = nb + (idx >> 4);
        float4 v = make_float4(0,0,0,0);
        if(node < NN) v = ((const float4*)x)[node*16 + (idx & 15)];
        xsm[idx] = v;
    }
    __syncthreads();
    for(int m=0;m<64;m++){
        int node = nb + m;
        if(node > NN) break;
        float acc = bias;
        #pragma unroll
        for(int q=0;q<16;q++){
            float4 xv = xsm[m*16 + q];
            acc = fmaf(xv.x, w[4*q+0], acc);
            acc = fmaf(xv.y, w[4*q+1], acc);
            acc = fmaf(xv.z, w[4*q+2], acc);
            acc = fmaf(xv.w, w[4*q+3], acc);
        }
        U[node*256 + p] = acc;
    }
}

// ---------------- LSTM aggregation (hot kernel, best: 6 nodes/warp) ----
__global__ void __launch_bounds__(256, 2) k_lstm(int L){
    extern __shared__ float smem[];
    float4* Wsm4 = (float4*)smem;            // 64KB
    float*  hsm  = smem + 16384;             // 48*64 = 12KB
    int et = blockIdx.y;
    int blk = L*4 + et;
    int tid = threadIdx.x;
    const float4* wp = (const float4*)(g_Wp + (size_t)blk*16384);
    #pragma unroll
    for(int r=0;r<16;r++) Wsm4[tid + r*256] = wp[tid + r*256];
    #pragma unroll
    for(int r=0;r<12;r++) hsm[tid + r*256] = 0.0f;
    __syncthreads();

    int warp = tid>>5, lane = tid&31;
    int nbase = blockIdx.x*48 + warp*6;
    const int* nbr = g_nbr + et*NN*MD;
    const float4* U4 = (const float4*)g_U[et];
    float c0[6], c1[6];
    int nodes[6];
    #pragma unroll
    for(int m=0;m<6;m++){
        c0[m]=0.f; c1[m]=0.f;
        int n = nbase+m; nodes[m] = (n<NN)?n:(NN-1);
    }
    float* hbase = hsm + warp*6*64;

    for(int t=0;t<MD;t++){
        u64 if0[6], go0[6], if1[6], go1[6];
        #pragma unroll
        for(int m=0;m<6;m++){
            int nb = __ldg(&nbr[nodes[m]*MD + t]);
            float4 a0 = __ldg(&U4[nb*64 + lane]);
            float4 a1 = __ldg(&U4[nb*64 + 32 + lane]);
            if0[m] = pkf(a0.x, a0.y); go0[m] = pkf(a0.z, a0.w);
            if1[m] = pkf(a1.x, a1.y); go1[m] = pkf(a1.z, a1.w);
        }
        #pragma unroll
        for(int k0=0;k0<64;k0+=4){
            float4 h4[6];
            #pragma unroll
            for(int m=0;m<6;m++) h4[m] = *(const float4*)&hbase[m*64 + k0];
            #pragma unroll
            for(int dk=0;dk<4;dk++){
                const ulonglong2 wa = *(const ulonglong2*)&Wsm4[(k0+dk)*64 + lane];
                const ulonglong2 wb = *(const ulonglong2*)&Wsm4[(k0+dk)*64 + 32 + lane];
                #pragma unroll
                for(int m=0;m<6;m++){
                    float hv = (dk==0)?h4[m].x:(dk==1)?h4[m].y:(dk==2)?h4[m].z:h4[m].w;
                    u64 hv2 = pkf(hv, hv);
                    if0[m] = fma2_(hv2, wa.x, if0[m]);
                    go0[m] = fma2_(hv2, wa.y, go0[m]);
                    if1[m] = fma2_(hv2, wb.x, if1[m]);
                    go1[m] = fma2_(hv2, wb.y, go1[m]);
                }
            }
        }
        __syncwarp();
        #pragma unroll
        for(int m=0;m<6;m++){
            float pi0, pf0, pg0, po0, pi1, pf1, pg1, po1;
            upk(if0[m], pi0, pf0); upk(go0[m], pg0, po0);
            upk(if1[m], pi1, pf1); upk(go1[m], pg1, po1);
            float i0=sigf(pi0), f0=sigf(pf0), g0=tanhf_(pg0), o0=sigf(po0);
            float i1=sigf(pi1), f1=sigf(pf1), g1=tanhf_(pg1), o1=sigf(po1);
            c0[m] = fmaf(f0, c0[m], i0*g0);
            c1[m] = fmaf(f1, c1[m], i1*g1);
            float h0 = o0*tanhf_(c0[m]);
            float h1 = o1*tanhf_(c1[m]);
            *(float2*)&hbase[m*64 + 2*lane] = make_float2(h0, h1);
        }
        __syncwarp();
    }
    float* agg = g_agg[et];
    #pragma unroll
    for(int m=0;m<6;m++){
        int n = nbase + m;
        if(n < NN){
            float2 hv = *(const float2*)&hbase[m*64 + 2*lane];
            ((float2*)(agg + n*64))[lane] = hv;
        }
    }
}

// ---- combine: 32 nodes/block, smem k-major weights; grid.y selects variant ----
__global__ void k_comb(const float* __restrict__ bl, int L,
                       int inSel, int outSel, int useRes){
    extern __shared__ float cs[];
    float* WlAT = cs;
    float* WlBT = cs + 4096;
    float* WrST = cs + 8192;
    float* A    = cs + 12288;
    float* B    = cs + 14336;
    float* X    = cs + 16384;
    float* blj  = cs + 18432;
    int v = blockIdx.y;          // 0: source side, 1: target side
    int ia = v ? (L*4+1) : (L*4+0);
    int ib = v ? (L*4+2) : (L*4+3);
    int etA = v ? 1 : 0;
    int etB = v ? 2 : 3;
    int isT = v;
    int tid = threadIdx.x;
    const float* wa = g_WlT + ia*4096;
    const float* wb = g_WlT + ib*4096;
    const float* ra = g_WrT + ia*4096;
    const float* rb = g_WrT + ib*4096;
    for(int i=tid;i<4096;i+=256){
        WlAT[i] = wa[i];
        WlBT[i] = wb[i];
        WrST[i] = ra[i] + rb[i];
    }
    if(tid < 64) blj[tid] = bl[ia*64+tid] + bl[ib*64+tid];
    int nb = blockIdx.x*32;
    const float* xin = isT ? g_tb[inSel] : g_sb[inSel];
    for(int i=tid;i<2048;i+=256){
        int node = nb + (i>>6); int c = i & 63;
        bool ok = node < NN;
        A[i] = ok ? g_agg[etA][node*64+c] : 0.0f;
        B[i] = ok ? g_agg[etB][node*64+c] : 0.0f;
        X[i] = ok ? xin[node*64+c] : 0.0f;
    }
    __syncthreads();
    int j = tid & 63, g = tid >> 6;
    float* out = isT ? g_tb[outSel] : g_sb[outSel];
    #pragma unroll
    for(int mi=0;mi<8;mi++){
        int m = g*8 + mi;
        int node = nb + m;
        float acc = blj[j];
        #pragma unroll 4
        for(int k=0;k<64;k++){
            acc = fmaf(A[m*64+k], WlAT[k*64+j], acc);
            acc = fmaf(B[m*64+k], WlBT[k*64+j], acc);
            acc = fmaf(X[m*64+k], WrST[k*64+j], acc);
        }
        acc *= 0.5f;
        if(useRes) acc += X[m*64+j];
        if(node < NN) out[node*64+j] = fmaxf(acc, 0.0f);
    }
}

// ---- edge head: 32 edges/block, smem k-major weights ----
__global__ void k_edge(const int* __restrict__ edges, const float* __restrict__ ea,
    const float* __restrict__ bg1, const float* __restrict__ Wg2, const float* __restrict__ bg2,
    const float* __restrict__ bm1, const float* __restrict__ bm2, const float* __restrict__ bm3,
    float* __restrict__ out){
    extern __shared__ float es[];
    float* Wg1T = es;               // 8192
    float* Wm1T = es + 8192;        // 5120
    float* Wm2T = es + 13312;       // 2048
    float* Wm3T = es + 15360;       // 64
    float* cvec = es + 15424;       // 256
    float* se   = es + 15680;       // 2048
    float* te   = es + 17728;       // 2048
    float* cat  = es + 19776;       // 2560
    float* h1   = es + 22336;       // 2048
    float* h2   = es + 24384;       // 1024
    float* red  = es + 25408;       // 64
    __shared__ int sidx[32], tidx[32];
    int tid = threadIdx.x;
    for(int i=tid;i<8192;i+=256) Wg1T[i] = g_Wg1T[i];
    for(int i=tid;i<5120;i+=256) Wm1T[i] = g_Wm1T[i];
    for(int i=tid;i<2048;i+=256) Wm2T[i] = g_Wm2T[i];
    if(tid < 64)  Wm3T[tid] = g_Wm3T[tid];
    if(tid < 64)  cvec[tid] = bg1[tid];
    else if(tid < 128) cvec[tid] = Wg2[tid-64];
    else if(tid < 192) cvec[tid] = bm1[tid-128];
    else if(tid < 224) cvec[tid] = bm2[tid-192];
    else if(tid == 224) cvec[224] = bm3[0];
    else if(tid == 225) cvec[225] = bm3[1];
    else if(tid == 226) cvec[226] = bg2[0];
    int ebase = blockIdx.x*32;
    if(tid < 32){
        sidx[tid] = edges[4*EE + ebase + tid];
        tidx[tid] = edges[5*EE + ebase + tid];
    }
    __syncthreads();
    for(int i=tid;i<2048;i+=256){
        int e = i >> 6, c = i & 63;
        se[i] = g_sb[1][sidx[e]*64 + c];
        te[i] = g_tb[1][tidx[e]*64 + c];
    }
    __syncthreads();
    int j = tid & 63, g = tid >> 6;
    int half = (tid >> 5) & 1;
    // Phase A: gate hidden dot Wg2, warp-reduced
    #pragma unroll
    for(int ei=0;ei<8;ei++){
        int e = g*8 + ei;
        float a = cvec[j];
        #pragma unroll 4
        for(int k=0;k<64;k++) a = fmaf(se[e*64+k], Wg1T[k*64+j], a);
        #pragma unroll 4
        for(int k=0;k<64;k++) a = fmaf(te[e*64+k], Wg1T[(64+k)*64+j], a);
        a = fmaxf(a, 0.0f);
        float v = a * cvec[64+j];
        #pragma unroll
        for(int off=16;off>0;off>>=1) v += __shfl_xor_sync(0xffffffffu, v, off);
        if((tid & 31) == 0) red[e*2 + half] = v;
    }
    __syncthreads();
    // Phase B: gate value, er || ea
    #pragma unroll
    for(int ei=0;ei<8;ei++){
        int e = g*8 + ei;
        float gv = sigf(red[e*2] + red[e*2+1] + cvec[226]);
        cat[e*80 + j] = gv*se[e*64+j] + (1.0f-gv)*te[e*64+j];
        if(j < 16) cat[e*80 + 64 + j] = ea[(ebase+e)*16 + j];
    }
    __syncthreads();
    // Phase C: m1
    #pragma unroll
    for(int ei=0;ei<8;ei++){
        int e = g*8 + ei;
        float m = cvec[128+j];
        #pragma unroll 4
        for(int k=0;k<80;k++) m = fmaf(cat[e*80+k], Wm1T[k*64+j], m);
        h1[e*64+j] = fmaxf(m, 0.0f);
    }
    __syncthreads();
    // Phase D: m2 (j<32)
    if(j < 32){
        #pragma unroll
        for(int ei=0;ei<8;ei++){
            int e = g*8 + ei;
            float m = cvec[192+j];
            #pragma unroll 4
            for(int k=0;k<64;k++) m = fmaf(h1[e*64+k], Wm2T[k*32+j], m);
            h2[e*32+j] = fmaxf(m, 0.0f);
        }
    }
    __syncthreads();
    // Phase E: m3 (j<2)
    if(j < 2){
        #pragma unroll
        for(int ei=0;ei<8;ei++){
            int e = g*8 + ei;
            float o = cvec[224+j];
            #pragma unroll
            for(int k=0;k<32;k++) o = fmaf(h2[e*32+k], Wm3T[k*2+j], o);
            out[(ebase+e)*2 + j] = o;
        }
    }
}

// ---------------- host launcher ----------------
extern "C" void kernel_launch(void* const* d_in, const int* in_sizes, int n_in,
                              void* d_out, int out_size){
    const float* x_source = (const float*)d_in[0];
    const float* x_target = (const float*)d_in[1];
    const int*   edges    = (const int*)  d_in[2];
    const float* ea       = (const float*)d_in[3];
    const float* We_s1=(const float*)d_in[4];  const float* be_s1=(const float*)d_in[5];
    const float* We_s2=(const float*)d_in[6];  const float* be_s2=(const float*)d_in[7];
    const float* We_t1=(const float*)d_in[8];  const float* be_t1=(const float*)d_in[9];
    const float* We_t2=(const float*)d_in[10]; const float* be_t2=(const float*)d_in[11];
    const float* Wih=(const float*)d_in[12];   const float* Whh=(const float*)d_in[13];
    const float* bih=(const float*)d_in[14];   const float* bhh=(const float*)d_in[15];
    const float* Wl =(const float*)d_in[16];   const float* bl =(const float*)d_in[17];
    const float* Wr =(const float*)d_in[18];
    const float* Wg1=(const float*)d_in[19];   const float* bg1=(const float*)d_in[20];
    const float* Wg2=(const float*)d_in[21];   const float* bg2=(const float*)d_in[22];
    const float* Wm1=(const float*)d_in[23];   const float* bm1=(const float*)d_in[24];
    const float* Wm2=(const float*)d_in[25];   const float* bm2=(const float*)d_in[26];
    const float* Wm3=(const float*)d_in[27];   const float* bm3=(const float*)d_in[28];
    float* out = (float*)d_out;

    cudaFuncSetAttribute(k_lstm, cudaFuncAttributeMaxDynamicSharedMemorySize, 77824);
    cudaFuncSetAttribute(k_comb, cudaFuncAttributeMaxDynamicSharedMemorySize, 75776);
    cudaFuncSetAttribute(k_edge, cudaFuncAttributeMaxDynamicSharedMemorySize, 102400);

    k_prep0   <<<(PREP0_TOTAL+255)/256, 256>>>(Whh, Wih, bih, bhh,
                                               Wl, Wr, Wg1, Wm1, Wm2, Wm3,
                                               We_s1, We_s2, We_t1, We_t2);
    k_degree  <<<(4*EE+255)/256, 256>>>(edges);
    k_scan    <<<4, 1024>>>();
    k_scatter <<<(4*EE+255)/256, 256>>>(edges);
    k_buildnbr<<<(4*NN+127)/128, 128>>>();
    k_enc     <<<dim3(313,2), 256>>>(x_source, x_target, be_s1, be_s2, be_t1, be_t2);

    for(int L=0; L<3; L++){
        int in = L & 1, o = 1 - in;
        k_U   <<<dim3(157,4), 256>>>(L, in);
        k_lstm<<<dim3(209,4), 256, 77824>>>(L);
        k_comb<<<dim3(313,2), 256, 75776>>>(bl, L, in, o, (L>0)?1:0);
    }
    k_edge<<<1250, 256, 102400>>>(edges, ea, bg1, Wg2, bg2, bm1, bm2, bm3, out);
}